// round 13
// baseline (speedup 1.0000x reference)
#include <cuda_runtime.h>
#include <math.h>
#include <stdint.h>

typedef unsigned long long ull;

// ---------------- problem constants ----------------
#define B 2
#define C 192
#define HEADS 6
#define ZP 32
#define NPOS (B*ZP*ZP*ZP)          // 65536
#define NW 256
#define DEPTH 4
#define TBL 675

// weight scratch offsets (floats)
#define QO 0
#define PO 442368
#define F1O 589824
#define F2O 1179648
#define RO 1769472
#define PEO 1794048
#define WT_TOTAL 1818624

// ---------------- scratch ----------------
__device__ float g_e  [(size_t)NPOS * C];
__device__ float g_w  [(size_t)NPOS * C];
__device__ float g_qkv[(size_t)NPOS * 3 * C];
__device__ float g_o  [(size_t)NPOS * C];
__device__ float g_h  [(size_t)NPOS * 4 * C];
__device__ float g_wt [WT_TOTAL];
__device__ float g_bias[DEPTH * HEADS * 128 * 128];
__device__ float g_zeros[192];

// ---------------- helpers ----------------
__device__ __forceinline__ float gelu_f(float v){
    return 0.5f * v * (1.0f + erff(v * 0.70710678118654752f));
}
__device__ __forceinline__ void mma_tf32(float* d, const uint32_t* a, const uint32_t* b){
    asm volatile(
        "mma.sync.aligned.m16n8k8.row.col.f32.tf32.tf32.f32 "
        "{%0,%1,%2,%3}, {%4,%5,%6,%7}, {%8,%9}, {%0,%1,%2,%3};"
        : "+f"(d[0]), "+f"(d[1]), "+f"(d[2]), "+f"(d[3])
        : "r"(a[0]), "r"(a[1]), "r"(a[2]), "r"(a[3]), "r"(b[0]), "r"(b[1]));
}
__device__ __forceinline__ float tf32_rna(float x){
    uint32_t r; asm("cvt.rna.tf32.f32 %0, %1;" : "=r"(r) : "f"(x));
    return __uint_as_float(r);
}
__device__ __forceinline__ uint32_t smem_u32(const void* p){
    uint32_t a;
    asm("{ .reg .u64 t; cvta.to.shared.u64 t, %1; cvt.u32.u64 %0, t; }" : "=r"(a) : "l"(p));
    return a;
}
__device__ __forceinline__ void cp16(uint32_t d, const void* s){
    asm volatile("cp.async.cg.shared.global [%0], [%1], 16;" :: "r"(d), "l"(s));
}
__device__ __forceinline__ void cp_commit(){
    asm volatile("cp.async.commit_group;");
}
template<int Npend>
__device__ __forceinline__ void cp_wait(){
    asm volatile("cp.async.wait_group %0;" :: "n"(Npend) : "memory");
}

// ================= fused setup: weight transposes + rounding + bias table =================
__global__ void setup_kernel(const float* __restrict__ qkv_w, const float* __restrict__ proj_w,
                             const float* __restrict__ fc1_w, const float* __restrict__ fc2_w,
                             const float* __restrict__ rec_w, const float* __restrict__ pe_w,
                             const float* __restrict__ rpb)
{
    int idx = blockIdx.x * 256 + threadIdx.x;
    if (idx < 442368) {
        int d = idx / 110592, r = idx % 110592;
        int k = r / 576, n = r % 576;
        g_wt[QO + d * 110592 + n * 192 + k] = tf32_rna(qkv_w[idx]);
        return;
    }
    idx -= 442368;
    if (idx < 147456) {
        int d = idx / 36864, r = idx % 36864;
        int k = r / 192, n = r % 192;
        g_wt[PO + d * 36864 + n * 192 + k] = tf32_rna(proj_w[idx]);
        return;
    }
    idx -= 147456;
    if (idx < 589824) {
        int d = idx / 147456, r = idx % 147456;
        int k = r / 768, n = r % 768;
        g_wt[F1O + d * 147456 + n * 192 + k] = tf32_rna(fc1_w[idx]);
        return;
    }
    idx -= 589824;
    if (idx < 589824) {
        int d = idx / 147456, r = idx % 147456;
        int k = r / 192, n = r % 192;
        g_wt[F2O + d * 147456 + n * 768 + k] = tf32_rna(fc2_w[idx]);
        return;
    }
    idx -= 589824;
    if (idx < 24576) {
        int k = idx / 128, n = idx % 128;
        g_wt[RO + n * 192 + k] = tf32_rna(rec_w[idx]);
        return;
    }
    idx -= 24576;
    if (idx < 24576) {
        g_wt[PEO + idx] = tf32_rna(pe_w[idx]);
        return;
    }
    idx -= 24576;
    if (idx < DEPTH * HEADS * 16384) {
        int d = idx / 98304, r = idx % 98304;
        int h = r >> 14, n = (r >> 7) & 127, m = r & 127;
        int zn = n >> 6, hn = (n >> 3) & 7, wn = n & 7;
        int zm = m >> 6, hm = (m >> 3) & 7, wm = m & 7;
        int bi = (zn - zm + 1) * 225 + (hn - hm + 7) * 15 + (wn - wm + 7);
        g_bias[idx] = rpb[((size_t)d * TBL + bi) * HEADS + h];
    }
}
#define SETUP_TOTAL (442368 + 147456 + 589824 + 589824 + 24576 + 24576 + DEPTH*HEADS*16384)

// ================= tf32 mma.sync GEMM, wide-N CTA tile =================
// D[M,N] = act(A[M,K] @ Wt[N,K]^T + bias).  CTA tile 128 x NT, threads = 2*NT,
// warps arranged 4M x (NT/64)N, warp tile 32x64 (acc 64 regs/thread). Kc=32.
template<int NT, int ACT, int BETA, int ROUT, int DUAL>
__global__ __launch_bounds__(2*NT)
void gemm_mma(const float* __restrict__ A, const float* __restrict__ Bw,
              const float* __restrict__ bias, float* __restrict__ Cm,
              float* __restrict__ Cm2, int N, int K)
{
    extern __shared__ float smem[];
    constexpr int T = 2 * NT;
    constexpr int NWN = NT / 64;                 // N-strips of warps
    constexpr int AIT = (1024 + T - 1) / T;      // A float4 loads per thread
    constexpr int ASZB = 128 * 36 * 4;
    constexpr int BSZB_ = NT * 36 * 4;
    const uint32_t uA = smem_u32(smem);
    const uint32_t uB = uA + 2 * ASZB;

    const int t = threadIdx.x;
    const int lane = t & 31, wid = t >> 5;
    const int warpM = (wid / NWN) * 32;
    const int warpN = (wid % NWN) * 64;
    const int g = lane >> 2, tg = lane & 3;
    const int bm = blockIdx.y << 7;
    const int bn = blockIdx.x * NT;
    const int K4 = K >> 2;
    const int nk = K >> 5;

    const float4* A4 = (const float4*)A;
    const float4* B4 = (const float4*)Bw;
    int aBase[AIT], aOff[AIT];
#pragma unroll
    for (int j = 0; j < AIT; j++) {
        int i = t + j * T;
        int row = (i >> 3) & 127, k4 = i & 7;
        aBase[j] = (bm + row) * K4 + k4;
        aOff[j] = (row * 36 + k4 * 4) * 4;
    }
    int bBase[4], bOff[4];
#pragma unroll
    for (int j = 0; j < 4; j++) {
        int i = t + j * T;
        int row = i >> 3, k4 = i & 7;
        bBase[j] = (bn + row) * K4 + k4;
        bOff[j] = (row * 36 + k4 * 4) * 4;
    }

#pragma unroll
    for (int j = 0; j < AIT; j++)
        if (AIT * T == 1024 || t + j * T < 1024) cp16(uA + aOff[j], &A4[aBase[j]]);
#pragma unroll
    for (int j = 0; j < 4; j++) cp16(uB + bOff[j], &B4[bBase[j]]);
    cp_commit();

    float acc[2][8][4];
#pragma unroll
    for (int mi = 0; mi < 2; mi++)
#pragma unroll
        for (int ni = 0; ni < 8; ni++)
#pragma unroll
            for (int j = 0; j < 4; j++) acc[mi][ni][j] = 0.f;

    for (int kt = 0; kt < nk; kt++) {
        cp_wait<0>();
        __syncthreads();
        const int buf = kt & 1;
        if (kt + 1 < nk) {
            const int nb = buf ^ 1;
            const int ko = (kt + 1) * 8;
#pragma unroll
            for (int j = 0; j < AIT; j++)
                if (AIT * T == 1024 || t + j * T < 1024)
                    cp16(uA + nb * ASZB + aOff[j], &A4[aBase[j] + ko]);
#pragma unroll
            for (int j = 0; j < 4; j++)
                cp16(uB + nb * BSZB_ + bOff[j], &B4[bBase[j] + ko]);
            cp_commit();
        }
        const uint32_t* Asu = (const uint32_t*)(smem + buf * 128 * 36);
        const uint32_t* Bsu = (const uint32_t*)(smem + 2 * 128 * 36 + buf * NT * 36);
#pragma unroll
        for (int ks = 0; ks < 4; ks++) {
            const int k0 = ks * 8;
            uint32_t af[2][4];
#pragma unroll
            for (int mi = 0; mi < 2; mi++) {
                int r = (warpM + mi * 16 + g) * 36 + k0 + tg;
                af[mi][0] = Asu[r];
                af[mi][1] = Asu[r + 8 * 36];
                af[mi][2] = Asu[r + 4];
                af[mi][3] = Asu[r + 8 * 36 + 4];
            }
#pragma unroll
            for (int ni = 0; ni < 8; ni++) {
                uint32_t bf[2];
                int r = (warpN + ni * 8 + g) * 36 + k0 + tg;
                bf[0] = Bsu[r];
                bf[1] = Bsu[r + 4];
                mma_tf32(acc[0][ni], af[0], bf);
                mma_tf32(acc[1][ni], af[1], bf);
            }
        }
        __syncthreads();
    }

#pragma unroll
    for (int mi = 0; mi < 2; mi++) {
        int r0 = bm + warpM + mi * 16 + g;
#pragma unroll
        for (int ni = 0; ni < 8; ni++) {
            int cb = bn + warpN + ni * 8 + 2 * tg;
            float b0 = bias[cb], b1 = bias[cb + 1];
            float v0 = acc[mi][ni][0] + b0, v1 = acc[mi][ni][1] + b1;
            float v2 = acc[mi][ni][2] + b0, v3 = acc[mi][ni][3] + b1;
            if (ACT) { v0 = gelu_f(v0); v1 = gelu_f(v1); v2 = gelu_f(v2); v3 = gelu_f(v3); }
            if (ROUT) { v0 = tf32_rna(v0); v1 = tf32_rna(v1); v2 = tf32_rna(v2); v3 = tf32_rna(v3); }
            size_t o0 = (size_t)r0 * N + cb;
            size_t o1 = (size_t)(r0 + 8) * N + cb;
            if (BETA) {
                float2 x0 = *(const float2*)&Cm[o0];
                float2 x1 = *(const float2*)&Cm[o1];
                v0 += x0.x; v1 += x0.y; v2 += x1.x; v3 += x1.y;
            }
            *(float2*)&Cm[o0] = make_float2(v0, v1);
            *(float2*)&Cm[o1] = make_float2(v2, v3);
            if (DUAL) {
                *(float2*)&Cm2[o0] = make_float2(tf32_rna(v0), tf32_rna(v1));
                *(float2*)&Cm2[o1] = make_float2(tf32_rna(v2), tf32_rna(v3));
            }
        }
    }
}

// ---------------- warp-per-token LayerNorm ----------------
__global__ __launch_bounds__(256)
void ln2_kernel(const float* __restrict__ src, float* __restrict__ dst,
                const float* __restrict__ g, const float* __restrict__ b, int mode, int rnd)
{
    const int lane = threadIdx.x & 31;
    const int tok = blockIdx.x * 8 + (threadIdx.x >> 5);
    int spos;
    if (mode == 0) {
        spos = tok;
    } else {
        int n = tok & 127, wi = (tok >> 7) & 255, bb = tok >> 15;
        int zw = wi >> 4, hw = (wi >> 2) & 3, ww = wi & 3;
        int z = zw * 2 + (n >> 6), h = hw * 8 + ((n >> 3) & 7), w = ww * 8 + (n & 7);
        if (mode == 2) { z = (z + 1) & 31; h = (h + 4) & 31; w = (w + 4) & 31; }
        spos = ((bb * 32 + z) * 32 + h) * 32 + w;
    }
    const float* sp = src + (size_t)spos * C;
    float v[6]; float s = 0.f, s2 = 0.f;
#pragma unroll
    for (int j = 0; j < 6; j++) { v[j] = sp[lane + 32*j]; s += v[j]; s2 += v[j]*v[j]; }
#pragma unroll
    for (int o = 16; o > 0; o >>= 1) {
        s  += __shfl_xor_sync(0xffffffffu, s,  o);
        s2 += __shfl_xor_sync(0xffffffffu, s2, o);
    }
    float m = s * (1.0f/192.0f);
    float rstd = rsqrtf(s2 * (1.0f/192.0f) - m*m + 1e-5f);
    float* dp = dst + (size_t)tok * C;
#pragma unroll
    for (int j = 0; j < 6; j++) {
        int c = lane + 32*j;
        float o2 = (v[j] - m) * rstd * g[c] + b[c];
        dp[c] = rnd ? tf32_rna(o2) : o2;
    }
}

// ---------------- fused window-merge + residual add + LayerNorm (dst rounded) ----------------
__global__ __launch_bounds__(256)
void lnfuse_kernel(float* __restrict__ e, const float* __restrict__ wwin,
                   float* __restrict__ dst,
                   const float* __restrict__ g, const float* __restrict__ b, int shifted)
{
    const int lane = threadIdx.x & 31;
    const int pos = blockIdx.x * 8 + (threadIdx.x >> 5);
    int ww2 = pos & 31, hh = (pos >> 5) & 31, z = (pos >> 10) & 31, bb = pos >> 15;
    int sz = shifted ? 1 : 0, s4 = shifted ? 4 : 0;
    int z2 = (z - sz) & 31, h2 = (hh - s4) & 31, w2 = (ww2 - s4) & 31;
    int wi = ((z2 >> 1) << 4) | ((h2 >> 3) << 2) | (w2 >> 3);
    int n  = ((z2 & 1) << 6) | ((h2 & 7) << 3) | (w2 & 7);
    int tok = (bb * 256 + wi) * 128 + n;

    float* ep = e + (size_t)pos * C;
    const float* wp = wwin + (size_t)tok * C;
    float v[6]; float s = 0.f, s2 = 0.f;
#pragma unroll
    for (int j = 0; j < 6; j++) {
        int c = lane + 32*j;
        float a = ep[c] + wp[c];
        ep[c] = a;
        v[j] = a; s += a; s2 += a*a;
    }
#pragma unroll
    for (int o = 16; o > 0; o >>= 1) {
        s  += __shfl_xor_sync(0xffffffffu, s,  o);
        s2 += __shfl_xor_sync(0xffffffffu, s2, o);
    }
    float m = s * (1.0f/192.0f);
    float rstd = rsqrtf(s2 * (1.0f/192.0f) - m*m + 1e-5f);
    float* dp = dst + (size_t)pos * C;
#pragma unroll
    for (int j = 0; j < 6; j++) {
        int c = lane + 32*j;
        dp[c] = tf32_rna((v[j] - m) * rstd * g[c] + b[c]);
    }
}

// ---------------- window attention: full tf32 MMA (QK^T and AV) ----------------
#define OQ 0
#define OK_ 4608
#define OV 9216
#define OS 13440
#define ORID 30336
#define ATTN_SMEM_F 30472

__global__ __launch_bounds__(256)
void attn2_kernel(const float* __restrict__ biasT, int shifted)
{
    extern __shared__ float sm[];
    float* Qn = sm + OQ;
    float* Kn = sm + OK_;
    float* Vt = sm + OV;
    float* Ss = sm + OS;
    int* rid_s = (int*)(sm + ORID);

    const int win = blockIdx.x;
    const int hh  = blockIdx.y;
    const int t = threadIdx.x;
    const int lane = t & 31, wid = t >> 5;
    const int g = lane >> 2, tg = lane & 3;
    const float scale = 0.1767766952966369f;
    const float* bl = biasT + (size_t)hh * 16384;

    for (int e = t; e < 4096; e += 256) {
        int n = e >> 5, d = e & 31;
        size_t base = ((size_t)(win * 128 + n)) * (3 * C) + hh * 32 + d;
        Qn[n * 36 + d] = tf32_rna(g_qkv[base] * scale);
        Kn[n * 36 + d] = tf32_rna(g_qkv[base + C]);
        Vt[d * 132 + n] = tf32_rna(g_qkv[base + 2 * C]);
    }
    int wloc = win & 255;
    int zw = wloc >> 4, hw = (wloc >> 2) & 3, ww = wloc & 3;
    if (shifted && t < 128) {
        int z = zw * 2 + (t >> 6), h = hw * 8 + ((t >> 3) & 7), w = ww * 8 + (t & 7);
        rid_s[t] = (z < 30 ? 0 : (z < 31 ? 1 : 2)) * 9
                 + (h < 24 ? 0 : (h < 28 ? 1 : 2)) * 3
                 + (w < 24 ? 0 : (w < 28 ? 1 : 2));
    }
    __syncthreads();

    {
        float sacc[16][4];
#pragma unroll
        for (int mi = 0; mi < 16; mi++)
#pragma unroll
            for (int j = 0; j < 4; j++) sacc[mi][j] = 0.f;
        const uint32_t* Qu = (const uint32_t*)Qn;
        const uint32_t* Ku = (const uint32_t*)Kn;
#pragma unroll
        for (int ks = 0; ks < 4; ks++) {
            const int k0 = ks * 8;
            uint32_t af[4];
            int ra = (wid * 16 + g) * 36 + k0 + tg;
            af[0] = Qu[ra];
            af[1] = Qu[ra + 8 * 36];
            af[2] = Qu[ra + 4];
            af[3] = Qu[ra + 8 * 36 + 4];
#pragma unroll
            for (int mi = 0; mi < 16; mi++) {
                uint32_t bf[2];
                int rb = (mi * 8 + g) * 36 + k0 + tg;
                bf[0] = Ku[rb];
                bf[1] = Ku[rb + 4];
                mma_tf32(sacc[mi], af, bf);
            }
        }
        int n0 = wid * 16 + g;
        int ridn0 = shifted ? rid_s[n0] : 0;
        int ridn1 = shifted ? rid_s[n0 + 8] : 0;
#pragma unroll
        for (int mi = 0; mi < 16; mi++) {
            int mb = mi * 8 + 2 * tg;
            float2 b0 = *(const float2*)&bl[n0 * 128 + mb];
            float2 b1 = *(const float2*)&bl[(n0 + 8) * 128 + mb];
            float v0 = sacc[mi][0] + b0.x, v1 = sacc[mi][1] + b0.y;
            float v2 = sacc[mi][2] + b1.x, v3 = sacc[mi][3] + b1.y;
            if (shifted) {
                int rm0 = rid_s[mb], rm1 = rid_s[mb + 1];
                if (rm0 != ridn0) v0 -= 100.0f;
                if (rm1 != ridn0) v1 -= 100.0f;
                if (rm0 != ridn1) v2 -= 100.0f;
                if (rm1 != ridn1) v3 -= 100.0f;
            }
            *(float2*)&Ss[n0 * 132 + mb] = make_float2(v0, v1);
            *(float2*)&Ss[(n0 + 8) * 132 + mb] = make_float2(v2, v3);
        }
    }
    __syncthreads();

    {
        int n = t >> 1, half = t & 1;
        float* row = &Ss[n * 132 + half * 64];
        float mx = -1e30f;
#pragma unroll
        for (int j = 0; j < 16; j++) {
            float4 v = *(const float4*)&row[j * 4];
            mx = fmaxf(mx, fmaxf(fmaxf(v.x, v.y), fmaxf(v.z, v.w)));
        }
        mx = fmaxf(mx, __shfl_xor_sync(0xffffffffu, mx, 1));
        float sum = 0.f;
#pragma unroll
        for (int j = 0; j < 16; j++) {
            float4 v = *(float4*)&row[j * 4];
            v.x = __expf(v.x - mx); v.y = __expf(v.y - mx);
            v.z = __expf(v.z - mx); v.w = __expf(v.w - mx);
            sum += v.x + v.y + v.z + v.w;
            *(float4*)&row[j * 4] = v;
        }
        sum += __shfl_xor_sync(0xffffffffu, sum, 1);
        float inv = 1.0f / sum;
#pragma unroll
        for (int j = 0; j < 16; j++) {
            float4 v = *(float4*)&row[j * 4];
            v.x = tf32_rna(v.x * inv); v.y = tf32_rna(v.y * inv);
            v.z = tf32_rna(v.z * inv); v.w = tf32_rna(v.w * inv);
            *(float4*)&row[j * 4] = v;
        }
    }
    __syncthreads();

    {
        float av[4][4];
#pragma unroll
        for (int ni = 0; ni < 4; ni++)
#pragma unroll
            for (int j = 0; j < 4; j++) av[ni][j] = 0.f;
        const uint32_t* Ps = (const uint32_t*)Ss;
        const uint32_t* Vu = (const uint32_t*)Vt;
#pragma unroll
        for (int ks = 0; ks < 16; ks++) {
            const int k0 = ks * 8;
            uint32_t af[4];
            int ra = (wid * 16 + g) * 132 + k0 + tg;
            af[0] = Ps[ra];
            af[1] = Ps[ra + 8 * 132];
            af[2] = Ps[ra + 4];
            af[3] = Ps[ra + 8 * 132 + 4];
#pragma unroll
            for (int ni = 0; ni < 4; ni++) {
                uint32_t bf[2];
                int rb = (ni * 8 + g) * 132 + k0 + tg;
                bf[0] = Vu[rb];
                bf[1] = Vu[rb + 4];
                mma_tf32(av[ni], af, bf);
            }
        }
#pragma unroll
        for (int ni = 0; ni < 4; ni++) {
            int n0 = wid * 16 + g;
            int d = ni * 8 + 2 * tg;
            size_t o0 = ((size_t)(win * 128 + n0)) * C + hh * 32 + d;
            size_t o1 = ((size_t)(win * 128 + n0 + 8)) * C + hh * 32 + d;
            *(float2*)&g_o[o0] = make_float2(tf32_rna(av[ni][0]), tf32_rna(av[ni][1]));
            *(float2*)&g_o[o1] = make_float2(tf32_rna(av[ni][2]), tf32_rna(av[ni][3]));
        }
    }
}

// ---------------- patch-embed gather (rounded) / recon scatter ----------------
__global__ void gather_kernel(const float* __restrict__ x, float* __restrict__ xg)
{
    int idx = blockIdx.x * blockDim.x + threadIdx.x;
    if (idx >= NPOS * 128) return;
    int t = idx & 127, pos = idx >> 7;
    int w = pos & 31, h = (pos >> 5) & 31, z = (pos >> 10) & 31, b = pos >> 15;
    int c4 = t >> 5, i = (t >> 4) & 1, j = (t >> 2) & 3, k = t & 3;
    xg[idx] = tf32_rna(x[((((size_t)b * 4 + c4) * 64 + 2 * z + i) * 128 + 4 * h + j) * 128 + 4 * w + k]);
}

__global__ void scatter_kernel(const float* __restrict__ rec, const float* __restrict__ rec_b,
                               float* __restrict__ out)
{
    int idx = blockIdx.x * blockDim.x + threadIdx.x;
    if (idx >= NPOS * 128) return;
    int t = idx & 127, pos = idx >> 7;
    int w = pos & 31, h = (pos >> 5) & 31, z = (pos >> 10) & 31, b = pos >> 15;
    int o = t >> 5, i = (t >> 4) & 1, j = (t >> 2) & 3, k = t & 3;
    out[((((size_t)b * 4 + o) * 64 + 2 * z + i) * 128 + 4 * h + j) * 128 + 4 * w + k]
        = rec[idx] + rec_b[o];
}

// ---------------- host launcher ----------------
extern "C" void kernel_launch(void* const* d_in, const int* in_sizes, int n_in,
                              void* d_out, int out_size)
{
    const float* x       = (const float*)d_in[0];
    const float* pe_w    = (const float*)d_in[1];
    const float* pe_b    = (const float*)d_in[2];
    const float* pe_ln_g = (const float*)d_in[3];
    const float* pe_ln_b = (const float*)d_in[4];
    const float* ln1_g   = (const float*)d_in[5];
    const float* ln1_b   = (const float*)d_in[6];
    const float* qkv_w   = (const float*)d_in[7];
    const float* qkv_b   = (const float*)d_in[8];
    const float* proj_w  = (const float*)d_in[9];
    const float* proj_b  = (const float*)d_in[10];
    const float* rpb     = (const float*)d_in[11];
    const float* ln2_g   = (const float*)d_in[12];
    const float* ln2_b   = (const float*)d_in[13];
    const float* fc1_w   = (const float*)d_in[14];
    const float* fc1_b   = (const float*)d_in[15];
    const float* fc2_w   = (const float*)d_in[16];
    const float* fc2_b   = (const float*)d_in[17];
    const float* rec_w   = (const float*)d_in[18];
    const float* rec_b   = (const float*)d_in[19];
    float* out = (float*)d_out;

    float *e, *w, *qkv, *h, *o, *wt, *bias, *zeros;
    cudaGetSymbolAddress((void**)&e,     g_e);
    cudaGetSymbolAddress((void**)&w,     g_w);
    cudaGetSymbolAddress((void**)&qkv,   g_qkv);
    cudaGetSymbolAddress((void**)&h,     g_h);
    cudaGetSymbolAddress((void**)&o,     g_o);
    cudaGetSymbolAddress((void**)&wt,    g_wt);
    cudaGetSymbolAddress((void**)&bias,  g_bias);
    cudaGetSymbolAddress((void**)&zeros, g_zeros);

    const int ATTN_SMEM = ATTN_SMEM_F * (int)sizeof(float);
    cudaFuncSetAttribute(attn2_kernel, cudaFuncAttributeMaxDynamicSharedMemorySize, ATTN_SMEM);
    const int GS192 = (2 * 128 * 36 + 2 * 192 * 36) * 4;   // 92160
    const int GS128 = (2 * 128 * 36 + 2 * 128 * 36) * 4;   // 73728
    cudaFuncSetAttribute(gemm_mma<192,0,0,0,0>, cudaFuncAttributeMaxDynamicSharedMemorySize, GS192);
    cudaFuncSetAttribute(gemm_mma<192,1,0,1,0>, cudaFuncAttributeMaxDynamicSharedMemorySize, GS192);
    cudaFuncSetAttribute(gemm_mma<192,0,1,0,0>, cudaFuncAttributeMaxDynamicSharedMemorySize, GS192);
    cudaFuncSetAttribute(gemm_mma<192,0,1,0,1>, cudaFuncAttributeMaxDynamicSharedMemorySize, GS192);
    cudaFuncSetAttribute(gemm_mma<128,0,0,0,0>, cudaFuncAttributeMaxDynamicSharedMemorySize, GS128);

    setup_kernel<<<(SETUP_TOTAL + 255) / 256, 256>>>(qkv_w, proj_w, fc1_w, fc2_w, rec_w, pe_w, rpb);

    gather_kernel<<<(NPOS * 128) / 256, 256>>>(x, h);
    gemm_mma<192,0,0,0,0><<<dim3(1, NPOS/128), 384, GS192>>>(h, wt + PEO, pe_b, w, e, 192, 128);
    ln2_kernel<<<NPOS / 8, 256>>>(w, e, pe_ln_g, pe_ln_b, 0, 0);

    for (int d = 0; d < DEPTH; d++) {
        int sh = d & 1;
        ln2_kernel<<<NPOS / 8, 256>>>(e, w, ln1_g + d * C, ln1_b + d * C, sh ? 2 : 1, 1);
        gemm_mma<192,0,0,0,0><<<dim3(3, NPOS/128), 384, GS192>>>(
            w, wt + QO + (size_t)d*110592, qkv_b + d * 3 * C, qkv, e, 3 * C, C);
        attn2_kernel<<<dim3(B * NW, HEADS), 256, ATTN_SMEM>>>(bias + (size_t)d * 98304, sh);
        gemm_mma<192,0,0,0,0><<<dim3(1, NPOS/128), 384, GS192>>>(
            o, wt + PO + (size_t)d*36864, proj_b + d * C, w, e, C, C);
        lnfuse_kernel<<<NPOS / 8, 256>>>(e, w, qkv, ln2_g + d * C, ln2_b + d * C, sh);
        gemm_mma<192,1,0,1,0><<<dim3(4, NPOS/128), 384, GS192>>>(
            qkv, wt + F1O + (size_t)d*147456, fc1_b + d * 4 * C, h, e, 4 * C, C);
        if (d < DEPTH - 1) {
            gemm_mma<192,0,1,0,0><<<dim3(1, NPOS/128), 384, GS192>>>(
                h, wt + F2O + (size_t)d*147456, fc2_b + d * C, e, w, C, 4 * C);
        } else {
            gemm_mma<192,0,1,0,1><<<dim3(1, NPOS/128), 384, GS192>>>(
                h, wt + F2O + (size_t)d*147456, fc2_b + d * C, e, w, C, 4 * C);
        }
    }

    gemm_mma<128,0,0,0,0><<<dim3(1, NPOS/128), 256, GS128>>>(w, wt + RO, zeros, qkv, e, 128, C);
    scatter_kernel<<<(NPOS * 128) / 256, 256>>>(qkv, rec_b, out);
}

// round 14
// speedup vs baseline: 1.0835x; 1.0835x over previous
#include <cuda_runtime.h>
#include <math.h>
#include <stdint.h>

typedef unsigned long long ull;

// ---------------- problem constants ----------------
#define B 2
#define C 192
#define HEADS 6
#define ZP 32
#define NPOS (B*ZP*ZP*ZP)          // 65536
#define NW 256
#define DEPTH 4
#define TBL 675

// weight scratch offsets (floats)
#define QO 0
#define PO 442368
#define F1O 589824
#define F2O 1179648
#define RO 1769472
#define PEO 1794048
#define WT_TOTAL 1818624

// ---------------- scratch ----------------
__device__ float g_e  [(size_t)NPOS * C];
__device__ float g_w  [(size_t)NPOS * C];
__device__ float g_qkv[(size_t)NPOS * 3 * C];
__device__ float g_o  [(size_t)NPOS * C];
__device__ float g_h  [(size_t)NPOS * 4 * C];
__device__ float g_wt [WT_TOTAL];
__device__ float g_bias[DEPTH * HEADS * 128 * 128];
__device__ float g_recb[128];
__device__ float g_zeros[192];

// ---------------- helpers ----------------
__device__ __forceinline__ float gelu_f(float v){
    return 0.5f * v * (1.0f + erff(v * 0.70710678118654752f));
}
__device__ __forceinline__ void mma_tf32(float* d, const uint32_t* a, const uint32_t* b){
    asm volatile(
        "mma.sync.aligned.m16n8k8.row.col.f32.tf32.tf32.f32 "
        "{%0,%1,%2,%3}, {%4,%5,%6,%7}, {%8,%9}, {%0,%1,%2,%3};"
        : "+f"(d[0]), "+f"(d[1]), "+f"(d[2]), "+f"(d[3])
        : "r"(a[0]), "r"(a[1]), "r"(a[2]), "r"(a[3]), "r"(b[0]), "r"(b[1]));
}
__device__ __forceinline__ float tf32_rna(float x){
    uint32_t r; asm("cvt.rna.tf32.f32 %0, %1;" : "=r"(r) : "f"(x));
    return __uint_as_float(r);
}
__device__ __forceinline__ uint32_t smem_u32(const void* p){
    uint32_t a;
    asm("{ .reg .u64 t; cvta.to.shared.u64 t, %1; cvt.u32.u64 %0, t; }" : "=r"(a) : "l"(p));
    return a;
}
__device__ __forceinline__ void cp16(uint32_t d, const void* s){
    asm volatile("cp.async.cg.shared.global [%0], [%1], 16;" :: "r"(d), "l"(s));
}
__device__ __forceinline__ void cp_commit(){
    asm volatile("cp.async.commit_group;");
}
template<int Npend>
__device__ __forceinline__ void cp_wait(){
    asm volatile("cp.async.wait_group %0;" :: "n"(Npend) : "memory");
}

// ================= fused setup =================
__global__ void setup_kernel(const float* __restrict__ qkv_w, const float* __restrict__ proj_w,
                             const float* __restrict__ fc1_w, const float* __restrict__ fc2_w,
                             const float* __restrict__ rec_w, const float* __restrict__ pe_w,
                             const float* __restrict__ rpb, const float* __restrict__ rec_b)
{
    int idx = blockIdx.x * 256 + threadIdx.x;
    if (idx < 442368) {
        int d = idx / 110592, r = idx % 110592;
        int k = r / 576, n = r % 576;
        g_wt[QO + d * 110592 + n * 192 + k] = tf32_rna(qkv_w[idx]);
        return;
    }
    idx -= 442368;
    if (idx < 147456) {
        int d = idx / 36864, r = idx % 36864;
        int k = r / 192, n = r % 192;
        g_wt[PO + d * 36864 + n * 192 + k] = tf32_rna(proj_w[idx]);
        return;
    }
    idx -= 147456;
    if (idx < 589824) {
        int d = idx / 147456, r = idx % 147456;
        int k = r / 768, n = r % 768;
        g_wt[F1O + d * 147456 + n * 192 + k] = tf32_rna(fc1_w[idx]);
        return;
    }
    idx -= 589824;
    if (idx < 589824) {
        int d = idx / 147456, r = idx % 147456;
        int k = r / 192, n = r % 192;
        g_wt[F2O + d * 147456 + n * 768 + k] = tf32_rna(fc2_w[idx]);
        return;
    }
    idx -= 589824;
    if (idx < 24576) {
        int k = idx / 128, n = idx % 128;
        g_wt[RO + n * 192 + k] = tf32_rna(rec_w[idx]);
        return;
    }
    idx -= 24576;
    if (idx < 24576) {
        g_wt[PEO + idx] = tf32_rna(pe_w[idx]);
        return;
    }
    idx -= 24576;
    if (idx < 128) {
        g_recb[idx] = rec_b[idx >> 5];
        return;
    }
    idx -= 128;
    if (idx < DEPTH * HEADS * 16384) {
        int d = idx / 98304, r = idx % 98304;
        int h = r >> 14, n = (r >> 7) & 127, m = r & 127;
        int zn = n >> 6, hn = (n >> 3) & 7, wn = n & 7;
        int zm = m >> 6, hm = (m >> 3) & 7, wm = m & 7;
        int bi = (zn - zm + 1) * 225 + (hn - hm + 7) * 15 + (wn - wm + 7);
        g_bias[idx] = rpb[((size_t)d * TBL + bi) * HEADS + h];
    }
}
#define SETUP_TOTAL (442368 + 147456 + 589824 + 589824 + 24576 + 24576 + 128 + DEPTH*HEADS*16384)

// ================= tf32 mma.sync GEMM (R12 config + PERM/SCAT epilogues) =================
#define ASZB (128 * 36 * 4)
#define BSZB (64 * 36 * 4)
template<int ACT, int BETA, int ROUT, int DUAL, int PERM, int SCAT>
__global__ __launch_bounds__(128)
void gemm_mma(const float* __restrict__ A, const float* __restrict__ Bw,
              const float* __restrict__ bias, float* __restrict__ Cm,
              float* __restrict__ Cm2, int N, int K, int sh)
{
    __shared__ float As[2][128 * 36];
    __shared__ float Bs[2][64 * 36];
    const int t = threadIdx.x;
    const int lane = t & 31, wid = t >> 5;
    const int warpM = wid * 32;
    const int g = lane >> 2, tg = lane & 3;
    const int bm = blockIdx.y << 7;
    const int bn = blockIdx.x << 6;
    const int K4 = K >> 2;
    const int nk = K >> 5;

    const float4* A4 = (const float4*)A;
    const float4* B4 = (const float4*)Bw;
    const int lrow = t >> 3;
    const int lk4  = t & 7;
    int aBase[8], aOff[8];
#pragma unroll
    for (int i = 0; i < 8; i++) {
        int row = lrow + i * 16;
        aBase[i] = (bm + row) * K4 + lk4;
        aOff[i] = (row * 36 + lk4 * 4) * 4;
    }
    int bBase[4], bOff[4];
#pragma unroll
    for (int i = 0; i < 4; i++) {
        int row = lrow + i * 16;
        bBase[i] = (bn + row) * K4 + lk4;
        bOff[i] = (row * 36 + lk4 * 4) * 4;
    }
    const uint32_t uA = smem_u32(&As[0][0]);
    const uint32_t uB = smem_u32(&Bs[0][0]);

#pragma unroll
    for (int i = 0; i < 8; i++) cp16(uA + aOff[i], &A4[aBase[i]]);
#pragma unroll
    for (int i = 0; i < 4; i++) cp16(uB + bOff[i], &B4[bBase[i]]);
    cp_commit();

    float acc[2][8][4];
#pragma unroll
    for (int mi = 0; mi < 2; mi++)
#pragma unroll
        for (int ni = 0; ni < 8; ni++)
#pragma unroll
            for (int j = 0; j < 4; j++) acc[mi][ni][j] = 0.f;

    for (int kt = 0; kt < nk; kt++) {
        cp_wait<0>();
        __syncthreads();
        const int buf = kt & 1;
        if (kt + 1 < nk) {
            const int nb = buf ^ 1;
            const int ko = (kt + 1) * 8;
#pragma unroll
            for (int i = 0; i < 8; i++) cp16(uA + nb * ASZB + aOff[i], &A4[aBase[i] + ko]);
#pragma unroll
            for (int i = 0; i < 4; i++) cp16(uB + nb * BSZB + bOff[i], &B4[bBase[i] + ko]);
            cp_commit();
        }
        const uint32_t* Asu = (const uint32_t*)As[buf];
        const uint32_t* Bsu = (const uint32_t*)Bs[buf];
#pragma unroll
        for (int ks = 0; ks < 4; ks++) {
            const int k0 = ks * 8;
            uint32_t af[2][4];
#pragma unroll
            for (int mi = 0; mi < 2; mi++) {
                int r = (warpM + mi * 16 + g) * 36 + k0 + tg;
                af[mi][0] = Asu[r];
                af[mi][1] = Asu[r + 8 * 36];
                af[mi][2] = Asu[r + 4];
                af[mi][3] = Asu[r + 8 * 36 + 4];
            }
#pragma unroll
            for (int ni = 0; ni < 8; ni++) {
                uint32_t bf[2];
                int r = (ni * 8 + g) * 36 + k0 + tg;
                bf[0] = Bsu[r];
                bf[1] = Bsu[r + 4];
                mma_tf32(acc[0][ni], af[0], bf);
                mma_tf32(acc[1][ni], af[1], bf);
            }
        }
        __syncthreads();
    }

#pragma unroll
    for (int mi = 0; mi < 2; mi++) {
        int rows[2] = { bm + warpM + mi * 16 + g, bm + warpM + mi * 16 + g + 8 };
        size_t rbase[2];
#pragma unroll
        for (int q = 0; q < 2; q++) {
            if (PERM) {
                int tok = rows[q];
                int n = tok & 127, wi = (tok >> 7) & 255, bb = tok >> 15;
                int z2 = (wi >> 4) * 2 + (n >> 6);
                int h2 = ((wi >> 2) & 3) * 8 + ((n >> 3) & 7);
                int w2 = (wi & 3) * 8 + (n & 7);
                if (sh) { z2 = (z2 + 1) & 31; h2 = (h2 + 4) & 31; w2 = (w2 + 4) & 31; }
                rbase[q] = (size_t)(((bb * 32 + z2) * 32 + h2) * 32 + w2) * N;
            } else if (!SCAT) {
                rbase[q] = (size_t)rows[q] * N;
            }
        }
#pragma unroll
        for (int ni = 0; ni < 8; ni++) {
            int cb = bn + ni * 8 + 2 * tg;
            float b0 = bias[cb], b1 = bias[cb + 1];
            float v0 = acc[mi][ni][0] + b0, v1 = acc[mi][ni][1] + b1;
            float v2 = acc[mi][ni][2] + b0, v3 = acc[mi][ni][3] + b1;
            if (ACT) { v0 = gelu_f(v0); v1 = gelu_f(v1); v2 = gelu_f(v2); v3 = gelu_f(v3); }
            if (ROUT) { v0 = tf32_rna(v0); v1 = tf32_rna(v1); v2 = tf32_rna(v2); v3 = tf32_rna(v3); }
            if (SCAT) {
                int c4 = cb >> 5, i2 = (cb >> 4) & 1, j = (cb >> 2) & 3, k = cb & 3;
                float2 vv[2] = { make_float2(v0, v1), make_float2(v2, v3) };
#pragma unroll
                for (int q = 0; q < 2; q++) {
                    int pos = rows[q];
                    int w = pos & 31, h = (pos >> 5) & 31, z = (pos >> 10) & 31, bb = pos >> 15;
                    size_t ofs = ((((size_t)bb * 4 + c4) * 64 + 2 * z + i2) * 128 + 4 * h + j) * 128 + 4 * w + k;
                    *(float2*)&Cm[ofs] = vv[q];
                }
            } else {
                size_t o0 = rbase[0] + cb;
                size_t o1 = rbase[1] + cb;
                if (BETA) {
                    float2 x0 = *(const float2*)&Cm[o0];
                    float2 x1 = *(const float2*)&Cm[o1];
                    v0 += x0.x; v1 += x0.y; v2 += x1.x; v3 += x1.y;
                }
                *(float2*)&Cm[o0] = make_float2(v0, v1);
                *(float2*)&Cm[o1] = make_float2(v2, v3);
                if (DUAL) {
                    *(float2*)&Cm2[o0] = make_float2(tf32_rna(v0), tf32_rna(v1));
                    *(float2*)&Cm2[o1] = make_float2(tf32_rna(v2), tf32_rna(v3));
                }
            }
        }
    }
}

// ================= patch-embed GEMM with fused gather =================
__global__ __launch_bounds__(128)
void gemm_pe(const float* __restrict__ x, const float* __restrict__ Bw,
             const float* __restrict__ bias, float* __restrict__ Cm)
{
    __shared__ float As[128 * 36];
    __shared__ float Bs[64 * 36];
    const int t = threadIdx.x;
    const int lane = t & 31, wid = t >> 5;
    const int warpM = wid * 32;
    const int g = lane >> 2, tg = lane & 3;
    const int bm = blockIdx.y << 7;
    const int bn = blockIdx.x << 6;
    const int N = 192;

    const float4* B4 = (const float4*)Bw;
    const int lrow = t >> 3;
    const int lk4  = t & 7;
    int aSm[8];
    int rw[8], rh[8], rz[8], rb[8];
#pragma unroll
    for (int i = 0; i < 8; i++) {
        int row = lrow + i * 16;
        aSm[i] = row * 36 + lk4 * 4;
        int pos = bm + row;
        rw[i] = pos & 31; rh[i] = (pos >> 5) & 31;
        rz[i] = (pos >> 10) & 31; rb[i] = pos >> 15;
    }
    int bBase[4], bOff[4];
#pragma unroll
    for (int i = 0; i < 4; i++) {
        int row = lrow + i * 16;
        bBase[i] = (bn + row) * 32 + lk4;     // K4 = 32
        bOff[i] = (row * 36 + lk4 * 4) * 4;
    }
    const uint32_t uB = smem_u32(&Bs[0]);

    float acc[2][8][4];
#pragma unroll
    for (int mi = 0; mi < 2; mi++)
#pragma unroll
        for (int ni = 0; ni < 8; ni++)
#pragma unroll
            for (int j = 0; j < 4; j++) acc[mi][ni][j] = 0.f;

    for (int kt = 0; kt < 4; kt++) {
        // A: gathered float4 load + rna + STS
        int tE0 = kt * 32 + lk4 * 4;
        int c4 = tE0 >> 5, i2 = (tE0 >> 4) & 1, j = (tE0 >> 2) & 3;
#pragma unroll
        for (int i = 0; i < 8; i++) {
            size_t addr = ((((size_t)rb[i] * 4 + c4) * 64 + 2 * rz[i] + i2) * 128 + 4 * rh[i] + j) * 128 + 4 * rw[i];
            float4 v = *(const float4*)&x[addr];
            v.x = tf32_rna(v.x); v.y = tf32_rna(v.y);
            v.z = tf32_rna(v.z); v.w = tf32_rna(v.w);
            *(float4*)&As[aSm[i]] = v;
        }
#pragma unroll
        for (int i = 0; i < 4; i++) cp16(uB + bOff[i], &B4[bBase[i] + kt * 8]);
        cp_commit();
        cp_wait<0>();
        __syncthreads();
        const uint32_t* Asu = (const uint32_t*)As;
        const uint32_t* Bsu = (const uint32_t*)Bs;
#pragma unroll
        for (int ks = 0; ks < 4; ks++) {
            const int k0 = ks * 8;
            uint32_t af[2][4];
#pragma unroll
            for (int mi = 0; mi < 2; mi++) {
                int r = (warpM + mi * 16 + g) * 36 + k0 + tg;
                af[mi][0] = Asu[r];
                af[mi][1] = Asu[r + 8 * 36];
                af[mi][2] = Asu[r + 4];
                af[mi][3] = Asu[r + 8 * 36 + 4];
            }
#pragma unroll
            for (int ni = 0; ni < 8; ni++) {
                uint32_t bf[2];
                int r = (ni * 8 + g) * 36 + k0 + tg;
                bf[0] = Bsu[r];
                bf[1] = Bsu[r + 4];
                mma_tf32(acc[0][ni], af[0], bf);
                mma_tf32(acc[1][ni], af[1], bf);
            }
        }
        __syncthreads();
    }

#pragma unroll
    for (int mi = 0; mi < 2; mi++) {
        int r0 = bm + warpM + mi * 16 + g;
#pragma unroll
        for (int ni = 0; ni < 8; ni++) {
            int cb = bn + ni * 8 + 2 * tg;
            float b0 = bias[cb], b1 = bias[cb + 1];
            size_t o0 = (size_t)r0 * N + cb;
            size_t o1 = (size_t)(r0 + 8) * N + cb;
            *(float2*)&Cm[o0] = make_float2(acc[mi][ni][0] + b0, acc[mi][ni][1] + b1);
            *(float2*)&Cm[o1] = make_float2(acc[mi][ni][2] + b0, acc[mi][ni][3] + b1);
        }
    }
}

// ---------------- warp-per-token LayerNorm ----------------
__global__ __launch_bounds__(256)
void ln2_kernel(const float* __restrict__ src, float* __restrict__ dst,
                const float* __restrict__ g, const float* __restrict__ b, int mode, int rnd)
{
    const int lane = threadIdx.x & 31;
    const int tok = blockIdx.x * 8 + (threadIdx.x >> 5);
    int spos;
    if (mode == 0) {
        spos = tok;
    } else {
        int n = tok & 127, wi = (tok >> 7) & 255, bb = tok >> 15;
        int zw = wi >> 4, hw = (wi >> 2) & 3, ww = wi & 3;
        int z = zw * 2 + (n >> 6), h = hw * 8 + ((n >> 3) & 7), w = ww * 8 + (n & 7);
        if (mode == 2) { z = (z + 1) & 31; h = (h + 4) & 31; w = (w + 4) & 31; }
        spos = ((bb * 32 + z) * 32 + h) * 32 + w;
    }
    const float* sp = src + (size_t)spos * C;
    float v[6]; float s = 0.f, s2 = 0.f;
#pragma unroll
    for (int j = 0; j < 6; j++) { v[j] = sp[lane + 32*j]; s += v[j]; s2 += v[j]*v[j]; }
#pragma unroll
    for (int o = 16; o > 0; o >>= 1) {
        s  += __shfl_xor_sync(0xffffffffu, s,  o);
        s2 += __shfl_xor_sync(0xffffffffu, s2, o);
    }
    float m = s * (1.0f/192.0f);
    float rstd = rsqrtf(s2 * (1.0f/192.0f) - m*m + 1e-5f);
    float* dp = dst + (size_t)tok * C;
#pragma unroll
    for (int j = 0; j < 6; j++) {
        int c = lane + 32*j;
        float o2 = (v[j] - m) * rstd * g[c] + b[c];
        dp[c] = rnd ? tf32_rna(o2) : o2;
    }
}

// ---------------- window attention: full tf32 MMA ----------------
#define OQ 0
#define OK_ 4608
#define OV 9216
#define OS 13440
#define ORID 30336
#define ATTN_SMEM_F 30472

__global__ __launch_bounds__(256)
void attn2_kernel(const float* __restrict__ biasT, int shifted)
{
    extern __shared__ float sm[];
    float* Qn = sm + OQ;
    float* Kn = sm + OK_;
    float* Vt = sm + OV;
    float* Ss = sm + OS;
    int* rid_s = (int*)(sm + ORID);

    const int win = blockIdx.x;
    const int hh  = blockIdx.y;
    const int t = threadIdx.x;
    const int lane = t & 31, wid = t >> 5;
    const int g = lane >> 2, tg = lane & 3;
    const float scale = 0.1767766952966369f;
    const float* bl = biasT + (size_t)hh * 16384;

    for (int e = t; e < 4096; e += 256) {
        int n = e >> 5, d = e & 31;
        size_t base = ((size_t)(win * 128 + n)) * (3 * C) + hh * 32 + d;
        Qn[n * 36 + d] = tf32_rna(g_qkv[base] * scale);
        Kn[n * 36 + d] = tf32_rna(g_qkv[base + C]);
        Vt[d * 132 + n] = tf32_rna(g_qkv[base + 2 * C]);
    }
    int wloc = win & 255;
    int zw = wloc >> 4, hw = (wloc >> 2) & 3, ww = wloc & 3;
    if (shifted && t < 128) {
        int z = zw * 2 + (t >> 6), h = hw * 8 + ((t >> 3) & 7), w = ww * 8 + (t & 7);
        rid_s[t] = (z < 30 ? 0 : (z < 31 ? 1 : 2)) * 9
                 + (h < 24 ? 0 : (h < 28 ? 1 : 2)) * 3
                 + (w < 24 ? 0 : (w < 28 ? 1 : 2));
    }
    __syncthreads();

    {
        float sacc[16][4];
#pragma unroll
        for (int mi = 0; mi < 16; mi++)
#pragma unroll
            for (int j = 0; j < 4; j++) sacc[mi][j] = 0.f;
        const uint32_t* Qu = (const uint32_t*)Qn;
        const uint32_t* Ku = (const uint32_t*)Kn;
#pragma unroll
        for (int ks = 0; ks < 4; ks++) {
            const int k0 = ks * 8;
            uint32_t af[4];
            int ra = (wid * 16 + g) * 36 + k0 + tg;
            af[0] = Qu[ra];
            af[1] = Qu[ra + 8 * 36];
            af[2] = Qu[ra + 4];
            af[3] = Qu[ra + 8 * 36 + 4];
#pragma unroll
            for (int mi = 0; mi < 16; mi++) {
                uint32_t bf[2];
                int rb = (mi * 8 + g) * 36 + k0 + tg;
                bf[0] = Ku[rb];
                bf[1] = Ku[rb + 4];
                mma_tf32(sacc[mi], af, bf);
            }
        }
        int n0 = wid * 16 + g;
        int ridn0 = shifted ? rid_s[n0] : 0;
        int ridn1 = shifted ? rid_s[n0 + 8] : 0;
#pragma unroll
        for (int mi = 0; mi < 16; mi++) {
            int mb = mi * 8 + 2 * tg;
            float2 b0 = *(const float2*)&bl[n0 * 128 + mb];
            float2 b1 = *(const float2*)&bl[(n0 + 8) * 128 + mb];
            float v0 = sacc[mi][0] + b0.x, v1 = sacc[mi][1] + b0.y;
            float v2 = sacc[mi][2] + b1.x, v3 = sacc[mi][3] + b1.y;
            if (shifted) {
                int rm0 = rid_s[mb], rm1 = rid_s[mb + 1];
                if (rm0 != ridn0) v0 -= 100.0f;
                if (rm1 != ridn0) v1 -= 100.0f;
                if (rm0 != ridn1) v2 -= 100.0f;
                if (rm1 != ridn1) v3 -= 100.0f;
            }
            *(float2*)&Ss[n0 * 132 + mb] = make_float2(v0, v1);
            *(float2*)&Ss[(n0 + 8) * 132 + mb] = make_float2(v2, v3);
        }
    }
    __syncthreads();

    {
        int n = t >> 1, half = t & 1;
        float* row = &Ss[n * 132 + half * 64];
        float mx = -1e30f;
#pragma unroll
        for (int j = 0; j < 16; j++) {
            float4 v = *(const float4*)&row[j * 4];
            mx = fmaxf(mx, fmaxf(fmaxf(v.x, v.y), fmaxf(v.z, v.w)));
        }
        mx = fmaxf(mx, __shfl_xor_sync(0xffffffffu, mx, 1));
        float sum = 0.f;
#pragma unroll
        for (int j = 0; j < 16; j++) {
            float4 v = *(float4*)&row[j * 4];
            v.x = __expf(v.x - mx); v.y = __expf(v.y - mx);
            v.z = __expf(v.z - mx); v.w = __expf(v.w - mx);
            sum += v.x + v.y + v.z + v.w;
            *(float4*)&row[j * 4] = v;
        }
        sum += __shfl_xor_sync(0xffffffffu, sum, 1);
        float inv = 1.0f / sum;
#pragma unroll
        for (int j = 0; j < 16; j++) {
            float4 v = *(float4*)&row[j * 4];
            v.x = tf32_rna(v.x * inv); v.y = tf32_rna(v.y * inv);
            v.z = tf32_rna(v.z * inv); v.w = tf32_rna(v.w * inv);
            *(float4*)&row[j * 4] = v;
        }
    }
    __syncthreads();

    {
        float av[4][4];
#pragma unroll
        for (int ni = 0; ni < 4; ni++)
#pragma unroll
            for (int j = 0; j < 4; j++) av[ni][j] = 0.f;
        const uint32_t* Ps = (const uint32_t*)Ss;
        const uint32_t* Vu = (const uint32_t*)Vt;
#pragma unroll
        for (int ks = 0; ks < 16; ks++) {
            const int k0 = ks * 8;
            uint32_t af[4];
            int ra = (wid * 16 + g) * 132 + k0 + tg;
            af[0] = Ps[ra];
            af[1] = Ps[ra + 8 * 132];
            af[2] = Ps[ra + 4];
            af[3] = Ps[ra + 8 * 132 + 4];
#pragma unroll
            for (int ni = 0; ni < 4; ni++) {
                uint32_t bf[2];
                int rb = (ni * 8 + g) * 132 + k0 + tg;
                bf[0] = Vu[rb];
                bf[1] = Vu[rb + 4];
                mma_tf32(av[ni], af, bf);
            }
        }
#pragma unroll
        for (int ni = 0; ni < 4; ni++) {
            int n0 = wid * 16 + g;
            int d = ni * 8 + 2 * tg;
            size_t o0 = ((size_t)(win * 128 + n0)) * C + hh * 32 + d;
            size_t o1 = ((size_t)(win * 128 + n0 + 8)) * C + hh * 32 + d;
            *(float2*)&g_o[o0] = make_float2(tf32_rna(av[ni][0]), tf32_rna(av[ni][1]));
            *(float2*)&g_o[o1] = make_float2(tf32_rna(av[ni][2]), tf32_rna(av[ni][3]));
        }
    }
}

// ---------------- host launcher ----------------
extern "C" void kernel_launch(void* const* d_in, const int* in_sizes, int n_in,
                              void* d_out, int out_size)
{
    const float* x       = (const float*)d_in[0];
    const float* pe_w    = (const float*)d_in[1];
    const float* pe_b    = (const float*)d_in[2];
    const float* pe_ln_g = (const float*)d_in[3];
    const float* pe_ln_b = (const float*)d_in[4];
    const float* ln1_g   = (const float*)d_in[5];
    const float* ln1_b   = (const float*)d_in[6];
    const float* qkv_w   = (const float*)d_in[7];
    const float* qkv_b   = (const float*)d_in[8];
    const float* proj_w  = (const float*)d_in[9];
    const float* proj_b  = (const float*)d_in[10];
    const float* rpb     = (const float*)d_in[11];
    const float* ln2_g   = (const float*)d_in[12];
    const float* ln2_b   = (const float*)d_in[13];
    const float* fc1_w   = (const float*)d_in[14];
    const float* fc1_b   = (const float*)d_in[15];
    const float* fc2_w   = (const float*)d_in[16];
    const float* fc2_b   = (const float*)d_in[17];
    const float* rec_w   = (const float*)d_in[18];
    const float* rec_b   = (const float*)d_in[19];
    float* out = (float*)d_out;

    float *e, *w, *qkv, *h, *o, *wt, *bias, *recb;
    cudaGetSymbolAddress((void**)&e,     g_e);
    cudaGetSymbolAddress((void**)&w,     g_w);
    cudaGetSymbolAddress((void**)&qkv,   g_qkv);
    cudaGetSymbolAddress((void**)&h,     g_h);
    cudaGetSymbolAddress((void**)&o,     g_o);
    cudaGetSymbolAddress((void**)&wt,    g_wt);
    cudaGetSymbolAddress((void**)&bias,  g_bias);
    cudaGetSymbolAddress((void**)&recb,  g_recb);

    const int ATTN_SMEM = ATTN_SMEM_F * (int)sizeof(float);
    cudaFuncSetAttribute(attn2_kernel, cudaFuncAttributeMaxDynamicSharedMemorySize, ATTN_SMEM);

    setup_kernel<<<(SETUP_TOTAL + 255) / 256, 256>>>(qkv_w, proj_w, fc1_w, fc2_w, rec_w, pe_w, rpb, rec_b);

    // patch embed: fused gather GEMM -> LN
    gemm_pe<<<dim3(3, NPOS/128), 128>>>(x, wt + PEO, pe_b, w);
    ln2_kernel<<<NPOS / 8, 256>>>(w, e, pe_ln_g, pe_ln_b, 0, 0);

    for (int d = 0; d < DEPTH; d++) {
        int sh = d & 1;
        ln2_kernel<<<NPOS / 8, 256>>>(e, w, ln1_g + d * C, ln1_b + d * C, sh ? 2 : 1, 1);
        gemm_mma<0,0,0,0,0,0><<<dim3(9, NPOS/128), 128>>>(
            w, wt + QO + (size_t)d*110592, qkv_b + d * 3 * C, qkv, e, 3 * C, C, 0);
        attn2_kernel<<<dim3(B * NW, HEADS), 256, ATTN_SMEM>>>(bias + (size_t)d * 98304, sh);
        // proj with fused un-window + residual add into e (PERM)
        gemm_mma<0,1,0,0,1,0><<<dim3(3, NPOS/128), 128>>>(
            o, wt + PO + (size_t)d*36864, proj_b + d * C, e, e, C, C, sh);
        // LN2 on updated e -> qkv (rounded)
        ln2_kernel<<<NPOS / 8, 256>>>(e, qkv, ln2_g + d * C, ln2_b + d * C, 0, 1);
        gemm_mma<1,0,1,0,0,0><<<dim3(12, NPOS/128), 128>>>(
            qkv, wt + F1O + (size_t)d*147456, fc1_b + d * 4 * C, h, e, 4 * C, C, 0);
        if (d < DEPTH - 1) {
            gemm_mma<0,1,0,0,0,0><<<dim3(3, NPOS/128), 128>>>(
                h, wt + F2O + (size_t)d*147456, fc2_b + d * C, e, w, C, 4 * C, 0);
        } else {
            gemm_mma<0,1,0,1,0,0><<<dim3(3, NPOS/128), 128>>>(
                h, wt + F2O + (size_t)d*147456, fc2_b + d * C, e, w, C, 4 * C, 0);
        }
    }

    // reconstruction with fused scatter (+rec_b via precomputed bias vector)
    gemm_mma<0,0,0,0,0,1><<<dim3(2, NPOS/128), 128>>>(w, wt + RO, recb, out, out, 128, C, 0);
}

// round 15
// speedup vs baseline: 1.0840x; 1.0005x over previous
#include <cuda_runtime.h>
#include <math.h>
#include <stdint.h>

typedef unsigned long long ull;

// ---------------- problem constants ----------------
#define B 2
#define C 192
#define HEADS 6
#define ZP 32
#define NPOS (B*ZP*ZP*ZP)          // 65536
#define NW 256
#define DEPTH 4
#define TBL 675

// weight scratch offsets (floats)
#define QO 0
#define PO 442368
#define F1O 589824
#define F2O 1179648
#define RO 1769472
#define PEO 1794048
#define WT_TOTAL 1818624

// ---------------- scratch ----------------
__device__ float g_e  [(size_t)NPOS * C];
__device__ float g_w  [(size_t)NPOS * C];
__device__ float g_qkv[(size_t)NPOS * 3 * C];
__device__ float g_o  [(size_t)NPOS * C];
__device__ float g_h  [(size_t)NPOS * 4 * C];
__device__ float g_wt [WT_TOTAL];
__device__ float g_bias[DEPTH * HEADS * 128 * 128];
__device__ float g_recb[128];

// ---------------- helpers ----------------
__device__ __forceinline__ float gelu_f(float v){
    return 0.5f * v * (1.0f + erff(v * 0.70710678118654752f));
}
__device__ __forceinline__ void mma_tf32(float* d, const uint32_t* a, const uint32_t* b){
    asm volatile(
        "mma.sync.aligned.m16n8k8.row.col.f32.tf32.tf32.f32 "
        "{%0,%1,%2,%3}, {%4,%5,%6,%7}, {%8,%9}, {%0,%1,%2,%3};"
        : "+f"(d[0]), "+f"(d[1]), "+f"(d[2]), "+f"(d[3])
        : "r"(a[0]), "r"(a[1]), "r"(a[2]), "r"(a[3]), "r"(b[0]), "r"(b[1]));
}
__device__ __forceinline__ float tf32_rna(float x){
    uint32_t r; asm("cvt.rna.tf32.f32 %0, %1;" : "=r"(r) : "f"(x));
    return __uint_as_float(r);
}
__device__ __forceinline__ uint32_t smem_u32(const void* p){
    uint32_t a;
    asm("{ .reg .u64 t; cvta.to.shared.u64 t, %1; cvt.u32.u64 %0, t; }" : "=r"(a) : "l"(p));
    return a;
}
__device__ __forceinline__ void cp16(uint32_t d, const void* s){
    asm volatile("cp.async.cg.shared.global [%0], [%1], 16;" :: "r"(d), "l"(s));
}
__device__ __forceinline__ void cp_commit(){
    asm volatile("cp.async.commit_group;");
}
template<int Npend>
__device__ __forceinline__ void cp_wait(){
    asm volatile("cp.async.wait_group %0;" :: "n"(Npend) : "memory");
}

// ================= fused setup =================
__global__ void setup_kernel(const float* __restrict__ qkv_w, const float* __restrict__ proj_w,
                             const float* __restrict__ fc1_w, const float* __restrict__ fc2_w,
                             const float* __restrict__ rec_w, const float* __restrict__ pe_w,
                             const float* __restrict__ rpb, const float* __restrict__ rec_b)
{
    int idx = blockIdx.x * 256 + threadIdx.x;
    if (idx < 442368) {
        int d = idx / 110592, r = idx % 110592;
        int k = r / 576, n = r % 576;
        g_wt[QO + d * 110592 + n * 192 + k] = tf32_rna(qkv_w[idx]);
        return;
    }
    idx -= 442368;
    if (idx < 147456) {
        int d = idx / 36864, r = idx % 36864;
        int k = r / 192, n = r % 192;
        g_wt[PO + d * 36864 + n * 192 + k] = tf32_rna(proj_w[idx]);
        return;
    }
    idx -= 147456;
    if (idx < 589824) {
        int d = idx / 147456, r = idx % 147456;
        int k = r / 768, n = r % 768;
        g_wt[F1O + d * 147456 + n * 192 + k] = tf32_rna(fc1_w[idx]);
        return;
    }
    idx -= 589824;
    if (idx < 589824) {
        int d = idx / 147456, r = idx % 147456;
        int k = r / 192, n = r % 192;
        g_wt[F2O + d * 147456 + n * 768 + k] = tf32_rna(fc2_w[idx]);
        return;
    }
    idx -= 589824;
    if (idx < 24576) {
        int k = idx / 128, n = idx % 128;
        g_wt[RO + n * 192 + k] = tf32_rna(rec_w[idx]);
        return;
    }
    idx -= 24576;
    if (idx < 24576) {
        g_wt[PEO + idx] = tf32_rna(pe_w[idx]);
        return;
    }
    idx -= 24576;
    if (idx < 128) {
        g_recb[idx] = rec_b[idx >> 5];
        return;
    }
    idx -= 128;
    if (idx < DEPTH * HEADS * 16384) {
        int d = idx / 98304, r = idx % 98304;
        int h = r >> 14, n = (r >> 7) & 127, m = r & 127;
        int zn = n >> 6, hn = (n >> 3) & 7, wn = n & 7;
        int zm = m >> 6, hm = (m >> 3) & 7, wm = m & 7;
        int bi = (zn - zm + 1) * 225 + (hn - hm + 7) * 15 + (wn - wm + 7);
        g_bias[idx] = rpb[((size_t)d * TBL + bi) * HEADS + h];
    }
}
#define SETUP_TOTAL (442368 + 147456 + 589824 + 589824 + 24576 + 24576 + 128 + DEPTH*HEADS*16384)

// ================= tf32 mma.sync GEMM (staged PERM/SCAT epilogues) =================
#define ASZB (128 * 36 * 4)
#define BSZB (64 * 36 * 4)
template<int ACT, int BETA, int ROUT, int DUAL, int PERM, int SCAT>
__global__ __launch_bounds__(128)
void gemm_mma(const float* __restrict__ A, const float* __restrict__ Bw,
              const float* __restrict__ bias, float* __restrict__ Cm,
              float* __restrict__ Cm2, int N, int K, int sh)
{
    __shared__ float As[2][128 * 36];
    __shared__ float Bs[2][64 * 36];
    const int t = threadIdx.x;
    const int lane = t & 31, wid = t >> 5;
    const int warpM = wid * 32;
    const int g = lane >> 2, tg = lane & 3;
    const int bm = blockIdx.y << 7;
    const int bn = blockIdx.x << 6;
    const int K4 = K >> 2;
    const int nk = K >> 5;

    const float4* A4 = (const float4*)A;
    const float4* B4 = (const float4*)Bw;
    const int lrow = t >> 3;
    const int lk4  = t & 7;
    int aBase[8], aOff[8];
#pragma unroll
    for (int i = 0; i < 8; i++) {
        int row = lrow + i * 16;
        aBase[i] = (bm + row) * K4 + lk4;
        aOff[i] = (row * 36 + lk4 * 4) * 4;
    }
    int bBase[4], bOff[4];
#pragma unroll
    for (int i = 0; i < 4; i++) {
        int row = lrow + i * 16;
        bBase[i] = (bn + row) * K4 + lk4;
        bOff[i] = (row * 36 + lk4 * 4) * 4;
    }
    const uint32_t uA = smem_u32(&As[0][0]);
    const uint32_t uB = smem_u32(&Bs[0][0]);

#pragma unroll
    for (int i = 0; i < 8; i++) cp16(uA + aOff[i], &A4[aBase[i]]);
#pragma unroll
    for (int i = 0; i < 4; i++) cp16(uB + bOff[i], &B4[bBase[i]]);
    cp_commit();

    float acc[2][8][4];
#pragma unroll
    for (int mi = 0; mi < 2; mi++)
#pragma unroll
        for (int ni = 0; ni < 8; ni++)
#pragma unroll
            for (int j = 0; j < 4; j++) acc[mi][ni][j] = 0.f;

    for (int kt = 0; kt < nk; kt++) {
        cp_wait<0>();
        __syncthreads();
        const int buf = kt & 1;
        if (kt + 1 < nk) {
            const int nb = buf ^ 1;
            const int ko = (kt + 1) * 8;
#pragma unroll
            for (int i = 0; i < 8; i++) cp16(uA + nb * ASZB + aOff[i], &A4[aBase[i] + ko]);
#pragma unroll
            for (int i = 0; i < 4; i++) cp16(uB + nb * BSZB + bOff[i], &B4[bBase[i] + ko]);
            cp_commit();
        }
        const uint32_t* Asu = (const uint32_t*)As[buf];
        const uint32_t* Bsu = (const uint32_t*)Bs[buf];
#pragma unroll
        for (int ks = 0; ks < 4; ks++) {
            const int k0 = ks * 8;
            uint32_t af[2][4];
#pragma unroll
            for (int mi = 0; mi < 2; mi++) {
                int r = (warpM + mi * 16 + g) * 36 + k0 + tg;
                af[mi][0] = Asu[r];
                af[mi][1] = Asu[r + 8 * 36];
                af[mi][2] = Asu[r + 4];
                af[mi][3] = Asu[r + 8 * 36 + 4];
            }
#pragma unroll
            for (int ni = 0; ni < 8; ni++) {
                uint32_t bf[2];
                int r = (ni * 8 + g) * 36 + k0 + tg;
                bf[0] = Bsu[r];
                bf[1] = Bsu[r + 4];
                mma_tf32(acc[0][ni], af[0], bf);
                mma_tf32(acc[1][ni], af[1], bf);
            }
        }
        __syncthreads();
    }

    if (PERM || SCAT) {
        // stage C-tile into smem (stride 72), then coalesced permuted writes
        float* Cs = &As[0][0];                       // 128*72 = 9216 floats, fits
#pragma unroll
        for (int mi = 0; mi < 2; mi++) {
            int r0 = warpM + mi * 16 + g;
#pragma unroll
            for (int ni = 0; ni < 8; ni++) {
                int cb = bn + ni * 8 + 2 * tg;
                float b0 = bias[cb], b1 = bias[cb + 1];
                *(float2*)&Cs[r0 * 72 + ni * 8 + 2 * tg] =
                    make_float2(acc[mi][ni][0] + b0, acc[mi][ni][1] + b1);
                *(float2*)&Cs[(r0 + 8) * 72 + ni * 8 + 2 * tg] =
                    make_float2(acc[mi][ni][2] + b0, acc[mi][ni][3] + b1);
            }
        }
        __syncthreads();
        if (PERM) {
            // 16 lanes per token: 256B contiguous RMW per token row of e
#pragma unroll
            for (int p = 0; p < 16; p++) {
                int ti = p * 8 + (t >> 4);
                int q4 = t & 15;
                int tok = bm + ti;
                int n = tok & 127, wi = (tok >> 7) & 255, bb = tok >> 15;
                int z2 = (wi >> 4) * 2 + (n >> 6);
                int h2 = ((wi >> 2) & 3) * 8 + ((n >> 3) & 7);
                int w2 = (wi & 3) * 8 + (n & 7);
                if (sh) { z2 = (z2 + 1) & 31; h2 = (h2 + 4) & 31; w2 = (w2 + 4) & 31; }
                size_t ofs = (size_t)(((bb * 32 + z2) * 32 + h2) * 32 + w2) * N + bn + q4 * 4;
                float4 v = *(float4*)&Cs[ti * 72 + q4 * 4];
                float4 old = *(const float4*)&Cm[ofs];
                v.x += old.x; v.y += old.y; v.z += old.z; v.w += old.w;
                *(float4*)&Cm[ofs] = v;
            }
        } else {
            // SCAT: one thread per token; 32 consecutive-w tokens -> 512B contiguous
            int pos = bm + t;
            int w = pos & 31, h = (pos >> 5) & 31, z = (pos >> 10) & 31, bb = pos >> 15;
#pragma unroll
            for (int combo = 0; combo < 16; combo++) {
                int cb0 = bn + combo * 4;
                int c4 = cb0 >> 5, i2 = (cb0 >> 4) & 1, j = (cb0 >> 2) & 3;
                size_t ofs = ((((size_t)bb * 4 + c4) * 64 + 2 * z + i2) * 128 + 4 * h + j) * 128 + 4 * w;
                *(float4*)&Cm[ofs] = *(float4*)&Cs[t * 72 + combo * 4];
            }
        }
        return;
    }

    // normal epilogue
#pragma unroll
    for (int mi = 0; mi < 2; mi++) {
        int r0 = bm + warpM + mi * 16 + g;
#pragma unroll
        for (int ni = 0; ni < 8; ni++) {
            int cb = bn + ni * 8 + 2 * tg;
            float b0 = bias[cb], b1 = bias[cb + 1];
            float v0 = acc[mi][ni][0] + b0, v1 = acc[mi][ni][1] + b1;
            float v2 = acc[mi][ni][2] + b0, v3 = acc[mi][ni][3] + b1;
            if (ACT) { v0 = gelu_f(v0); v1 = gelu_f(v1); v2 = gelu_f(v2); v3 = gelu_f(v3); }
            if (ROUT) { v0 = tf32_rna(v0); v1 = tf32_rna(v1); v2 = tf32_rna(v2); v3 = tf32_rna(v3); }
            size_t o0 = (size_t)r0 * N + cb;
            size_t o1 = (size_t)(r0 + 8) * N + cb;
            if (BETA) {
                float2 x0 = *(const float2*)&Cm[o0];
                float2 x1 = *(const float2*)&Cm[o1];
                v0 += x0.x; v1 += x0.y; v2 += x1.x; v3 += x1.y;
            }
            *(float2*)&Cm[o0] = make_float2(v0, v1);
            *(float2*)&Cm[o1] = make_float2(v2, v3);
            if (DUAL) {
                *(float2*)&Cm2[o0] = make_float2(tf32_rna(v0), tf32_rna(v1));
                *(float2*)&Cm2[o1] = make_float2(tf32_rna(v2), tf32_rna(v3));
            }
        }
    }
}

// ================= patch-embed GEMM with fused gather (overlapped) =================
__global__ __launch_bounds__(128)
void gemm_pe(const float* __restrict__ x, const float* __restrict__ Bw,
             const float* __restrict__ bias, float* __restrict__ Cm)
{
    __shared__ float As[128 * 36];
    __shared__ float Bs[64 * 36];
    const int t = threadIdx.x;
    const int lane = t & 31, wid = t >> 5;
    const int warpM = wid * 32;
    const int g = lane >> 2, tg = lane & 3;
    const int bm = blockIdx.y << 7;
    const int bn = blockIdx.x << 6;
    const int N = 192;

    const float4* B4 = (const float4*)Bw;
    const int lrow = t >> 3;
    const int lk4  = t & 7;
    int aSm[8];
    size_t abase[8];
#pragma unroll
    for (int i = 0; i < 8; i++) {
        int row = lrow + i * 16;
        aSm[i] = row * 36 + lk4 * 4;
        int pos = bm + row;
        int rw = pos & 31, rh = (pos >> 5) & 31, rz = (pos >> 10) & 31, rb = pos >> 15;
        abase[i] = (((size_t)rb * 4) * 64 + 2 * rz) * 16384 + (size_t)4 * rh * 128 + 4 * rw;
    }
    int bBase[4], bOff[4];
#pragma unroll
    for (int i = 0; i < 4; i++) {
        int row = lrow + i * 16;
        bBase[i] = (bn + row) * 32 + lk4;
        bOff[i] = (row * 36 + lk4 * 4) * 4;
    }
    const uint32_t uB = smem_u32(&Bs[0]);

    float acc[2][8][4];
#pragma unroll
    for (int mi = 0; mi < 2; mi++)
#pragma unroll
        for (int ni = 0; ni < 8; ni++)
#pragma unroll
            for (int j = 0; j < 4; j++) acc[mi][ni][j] = 0.f;

    // gather offset for channel block t0: c4 = t0>>5, i2 = (t0>>4)&1, j = (t0>>2)&3
    auto goff = [](int t0) -> size_t {
        int c4 = t0 >> 5, i2 = (t0 >> 4) & 1, j = (t0 >> 2) & 3;
        return ((size_t)c4 * 64 + i2) * 16384 + (size_t)j * 128;
    };

    float4 pa[8];
    {
        size_t go = goff(lk4 * 4);
#pragma unroll
        for (int i = 0; i < 8; i++) pa[i] = *(const float4*)&x[abase[i] + go];
    }

    for (int kt = 0; kt < 4; kt++) {
#pragma unroll
        for (int i = 0; i < 8; i++) {
            float4 v = pa[i];
            v.x = tf32_rna(v.x); v.y = tf32_rna(v.y);
            v.z = tf32_rna(v.z); v.w = tf32_rna(v.w);
            *(float4*)&As[aSm[i]] = v;
        }
#pragma unroll
        for (int i = 0; i < 4; i++) cp16(uB + bOff[i], &B4[bBase[i] + kt * 8]);
        cp_commit();
        if (kt < 3) {
            size_t go = goff((kt + 1) * 32 + lk4 * 4);
#pragma unroll
            for (int i = 0; i < 8; i++) pa[i] = *(const float4*)&x[abase[i] + go];
        }
        cp_wait<0>();
        __syncthreads();
        const uint32_t* Asu = (const uint32_t*)As;
        const uint32_t* Bsu = (const uint32_t*)Bs;
#pragma unroll
        for (int ks = 0; ks < 4; ks++) {
            const int k0 = ks * 8;
            uint32_t af[2][4];
#pragma unroll
            for (int mi = 0; mi < 2; mi++) {
                int r = (warpM + mi * 16 + g) * 36 + k0 + tg;
                af[mi][0] = Asu[r];
                af[mi][1] = Asu[r + 8 * 36];
                af[mi][2] = Asu[r + 4];
                af[mi][3] = Asu[r + 8 * 36 + 4];
            }
#pragma unroll
            for (int ni = 0; ni < 8; ni++) {
                uint32_t bf[2];
                int r = (ni * 8 + g) * 36 + k0 + tg;
                bf[0] = Bsu[r];
                bf[1] = Bsu[r + 4];
                mma_tf32(acc[0][ni], af[0], bf);
                mma_tf32(acc[1][ni], af[1], bf);
            }
        }
        __syncthreads();
    }

#pragma unroll
    for (int mi = 0; mi < 2; mi++) {
        int r0 = bm + warpM + mi * 16 + g;
#pragma unroll
        for (int ni = 0; ni < 8; ni++) {
            int cb = bn + ni * 8 + 2 * tg;
            float b0 = bias[cb], b1 = bias[cb + 1];
            size_t o0 = (size_t)r0 * N + cb;
            size_t o1 = (size_t)(r0 + 8) * N + cb;
            *(float2*)&Cm[o0] = make_float2(acc[mi][ni][0] + b0, acc[mi][ni][1] + b1);
            *(float2*)&Cm[o1] = make_float2(acc[mi][ni][2] + b0, acc[mi][ni][3] + b1);
        }
    }
}

// ---------------- warp-per-token LayerNorm ----------------
__global__ __launch_bounds__(256)
void ln2_kernel(const float* __restrict__ src, float* __restrict__ dst,
                const float* __restrict__ g, const float* __restrict__ b, int mode, int rnd)
{
    const int lane = threadIdx.x & 31;
    const int tok = blockIdx.x * 8 + (threadIdx.x >> 5);
    int spos;
    if (mode == 0) {
        spos = tok;
    } else {
        int n = tok & 127, wi = (tok >> 7) & 255, bb = tok >> 15;
        int zw = wi >> 4, hw = (wi >> 2) & 3, ww = wi & 3;
        int z = zw * 2 + (n >> 6), h = hw * 8 + ((n >> 3) & 7), w = ww * 8 + (n & 7);
        if (mode == 2) { z = (z + 1) & 31; h = (h + 4) & 31; w = (w + 4) & 31; }
        spos = ((bb * 32 + z) * 32 + h) * 32 + w;
    }
    const float* sp = src + (size_t)spos * C;
    float v[6]; float s = 0.f, s2 = 0.f;
#pragma unroll
    for (int j = 0; j < 6; j++) { v[j] = sp[lane + 32*j]; s += v[j]; s2 += v[j]*v[j]; }
#pragma unroll
    for (int o = 16; o > 0; o >>= 1) {
        s  += __shfl_xor_sync(0xffffffffu, s,  o);
        s2 += __shfl_xor_sync(0xffffffffu, s2, o);
    }
    float m = s * (1.0f/192.0f);
    float rstd = rsqrtf(s2 * (1.0f/192.0f) - m*m + 1e-5f);
    float* dp = dst + (size_t)tok * C;
#pragma unroll
    for (int j = 0; j < 6; j++) {
        int c = lane + 32*j;
        float o2 = (v[j] - m) * rstd * g[c] + b[c];
        dp[c] = rnd ? tf32_rna(o2) : o2;
    }
}

// ---------------- window attention: full tf32 MMA ----------------
#define OQ 0
#define OK_ 4608
#define OV 9216
#define OS 13440
#define ORID 30336
#define ATTN_SMEM_F 30472

__global__ __launch_bounds__(256)
void attn2_kernel(const float* __restrict__ biasT, int shifted)
{
    extern __shared__ float sm[];
    float* Qn = sm + OQ;
    float* Kn = sm + OK_;
    float* Vt = sm + OV;
    float* Ss = sm + OS;
    int* rid_s = (int*)(sm + ORID);

    const int win = blockIdx.x;
    const int hh  = blockIdx.y;
    const int t = threadIdx.x;
    const int lane = t & 31, wid = t >> 5;
    const int g = lane >> 2, tg = lane & 3;
    const float scale = 0.1767766952966369f;
    const float* bl = biasT + (size_t)hh * 16384;

    for (int e = t; e < 4096; e += 256) {
        int n = e >> 5, d = e & 31;
        size_t base = ((size_t)(win * 128 + n)) * (3 * C) + hh * 32 + d;
        Qn[n * 36 + d] = tf32_rna(g_qkv[base] * scale);
        Kn[n * 36 + d] = tf32_rna(g_qkv[base + C]);
        Vt[d * 132 + n] = tf32_rna(g_qkv[base + 2 * C]);
    }
    int wloc = win & 255;
    int zw = wloc >> 4, hw = (wloc >> 2) & 3, ww = wloc & 3;
    if (shifted && t < 128) {
        int z = zw * 2 + (t >> 6), h = hw * 8 + ((t >> 3) & 7), w = ww * 8 + (t & 7);
        rid_s[t] = (z < 30 ? 0 : (z < 31 ? 1 : 2)) * 9
                 + (h < 24 ? 0 : (h < 28 ? 1 : 2)) * 3
                 + (w < 24 ? 0 : (w < 28 ? 1 : 2));
    }
    __syncthreads();

    {
        float sacc[16][4];
#pragma unroll
        for (int mi = 0; mi < 16; mi++)
#pragma unroll
            for (int j = 0; j < 4; j++) sacc[mi][j] = 0.f;
        const uint32_t* Qu = (const uint32_t*)Qn;
        const uint32_t* Ku = (const uint32_t*)Kn;
#pragma unroll
        for (int ks = 0; ks < 4; ks++) {
            const int k0 = ks * 8;
            uint32_t af[4];
            int ra = (wid * 16 + g) * 36 + k0 + tg;
            af[0] = Qu[ra];
            af[1] = Qu[ra + 8 * 36];
            af[2] = Qu[ra + 4];
            af[3] = Qu[ra + 8 * 36 + 4];
#pragma unroll
            for (int mi = 0; mi < 16; mi++) {
                uint32_t bf[2];
                int rb = (mi * 8 + g) * 36 + k0 + tg;
                bf[0] = Ku[rb];
                bf[1] = Ku[rb + 4];
                mma_tf32(sacc[mi], af, bf);
            }
        }
        int n0 = wid * 16 + g;
        int ridn0 = shifted ? rid_s[n0] : 0;
        int ridn1 = shifted ? rid_s[n0 + 8] : 0;
#pragma unroll
        for (int mi = 0; mi < 16; mi++) {
            int mb = mi * 8 + 2 * tg;
            float2 b0 = *(const float2*)&bl[n0 * 128 + mb];
            float2 b1 = *(const float2*)&bl[(n0 + 8) * 128 + mb];
            float v0 = sacc[mi][0] + b0.x, v1 = sacc[mi][1] + b0.y;
            float v2 = sacc[mi][2] + b1.x, v3 = sacc[mi][3] + b1.y;
            if (shifted) {
                int rm0 = rid_s[mb], rm1 = rid_s[mb + 1];
                if (rm0 != ridn0) v0 -= 100.0f;
                if (rm1 != ridn0) v1 -= 100.0f;
                if (rm0 != ridn1) v2 -= 100.0f;
                if (rm1 != ridn1) v3 -= 100.0f;
            }
            *(float2*)&Ss[n0 * 132 + mb] = make_float2(v0, v1);
            *(float2*)&Ss[(n0 + 8) * 132 + mb] = make_float2(v2, v3);
        }
    }
    __syncthreads();

    {
        int n = t >> 1, half = t & 1;
        float* row = &Ss[n * 132 + half * 64];
        float mx = -1e30f;
#pragma unroll
        for (int j = 0; j < 16; j++) {
            float4 v = *(const float4*)&row[j * 4];
            mx = fmaxf(mx, fmaxf(fmaxf(v.x, v.y), fmaxf(v.z, v.w)));
        }
        mx = fmaxf(mx, __shfl_xor_sync(0xffffffffu, mx, 1));
        float sum = 0.f;
#pragma unroll
        for (int j = 0; j < 16; j++) {
            float4 v = *(float4*)&row[j * 4];
            v.x = __expf(v.x - mx); v.y = __expf(v.y - mx);
            v.z = __expf(v.z - mx); v.w = __expf(v.w - mx);
            sum += v.x + v.y + v.z + v.w;
            *(float4*)&row[j * 4] = v;
        }
        sum += __shfl_xor_sync(0xffffffffu, sum, 1);
        float inv = 1.0f / sum;
#pragma unroll
        for (int j = 0; j < 16; j++) {
            float4 v = *(float4*)&row[j * 4];
            v.x = tf32_rna(v.x * inv); v.y = tf32_rna(v.y * inv);
            v.z = tf32_rna(v.z * inv); v.w = tf32_rna(v.w * inv);
            *(float4*)&row[j * 4] = v;
        }
    }
    __syncthreads();

    {
        float av[4][4];
#pragma unroll
        for (int ni = 0; ni < 4; ni++)
#pragma unroll
            for (int j = 0; j < 4; j++) av[ni][j] = 0.f;
        const uint32_t* Ps = (const uint32_t*)Ss;
        const uint32_t* Vu = (const uint32_t*)Vt;
#pragma unroll
        for (int ks = 0; ks < 16; ks++) {
            const int k0 = ks * 8;
            uint32_t af[4];
            int ra = (wid * 16 + g) * 132 + k0 + tg;
            af[0] = Ps[ra];
            af[1] = Ps[ra + 8 * 132];
            af[2] = Ps[ra + 4];
            af[3] = Ps[ra + 8 * 132 + 4];
#pragma unroll
            for (int ni = 0; ni < 4; ni++) {
                uint32_t bf[2];
                int rb = (ni * 8 + g) * 132 + k0 + tg;
                bf[0] = Vu[rb];
                bf[1] = Vu[rb + 4];
                mma_tf32(av[ni], af, bf);
            }
        }
#pragma unroll
        for (int ni = 0; ni < 4; ni++) {
            int n0 = wid * 16 + g;
            int d = ni * 8 + 2 * tg;
            size_t o0 = ((size_t)(win * 128 + n0)) * C + hh * 32 + d;
            size_t o1 = ((size_t)(win * 128 + n0 + 8)) * C + hh * 32 + d;
            *(float2*)&g_o[o0] = make_float2(tf32_rna(av[ni][0]), tf32_rna(av[ni][1]));
            *(float2*)&g_o[o1] = make_float2(tf32_rna(av[ni][2]), tf32_rna(av[ni][3]));
        }
    }
}

// ---------------- host launcher ----------------
extern "C" void kernel_launch(void* const* d_in, const int* in_sizes, int n_in,
                              void* d_out, int out_size)
{
    const float* x       = (const float*)d_in[0];
    const float* pe_w    = (const float*)d_in[1];
    const float* pe_b    = (const float*)d_in[2];
    const float* pe_ln_g = (const float*)d_in[3];
    const float* pe_ln_b = (const float*)d_in[4];
    const float* ln1_g   = (const float*)d_in[5];
    const float* ln1_b   = (const float*)d_in[6];
    const float* qkv_w   = (const float*)d_in[7];
    const float* qkv_b   = (const float*)d_in[8];
    const float* proj_w  = (const float*)d_in[9];
    const float* proj_b  = (const float*)d_in[10];
    const float* rpb     = (const float*)d_in[11];
    const float* ln2_g   = (const float*)d_in[12];
    const float* ln2_b   = (const float*)d_in[13];
    const float* fc1_w   = (const float*)d_in[14];
    const float* fc1_b   = (const float*)d_in[15];
    const float* fc2_w   = (const float*)d_in[16];
    const float* fc2_b   = (const float*)d_in[17];
    const float* rec_w   = (const float*)d_in[18];
    const float* rec_b   = (const float*)d_in[19];
    float* out = (float*)d_out;

    float *e, *w, *qkv, *h, *o, *wt, *bias, *recb;
    cudaGetSymbolAddress((void**)&e,     g_e);
    cudaGetSymbolAddress((void**)&w,     g_w);
    cudaGetSymbolAddress((void**)&qkv,   g_qkv);
    cudaGetSymbolAddress((void**)&h,     g_h);
    cudaGetSymbolAddress((void**)&o,     g_o);
    cudaGetSymbolAddress((void**)&wt,    g_wt);
    cudaGetSymbolAddress((void**)&bias,  g_bias);
    cudaGetSymbolAddress((void**)&recb,  g_recb);

    const int ATTN_SMEM = ATTN_SMEM_F * (int)sizeof(float);
    cudaFuncSetAttribute(attn2_kernel, cudaFuncAttributeMaxDynamicSharedMemorySize, ATTN_SMEM);

    setup_kernel<<<(SETUP_TOTAL + 255) / 256, 256>>>(qkv_w, proj_w, fc1_w, fc2_w, rec_w, pe_w, rpb, rec_b);

    // patch embed: fused gather GEMM -> LN
    gemm_pe<<<dim3(3, NPOS/128), 128>>>(x, wt + PEO, pe_b, w);
    ln2_kernel<<<NPOS / 8, 256>>>(w, e, pe_ln_g, pe_ln_b, 0, 0);

    for (int d = 0; d < DEPTH; d++) {
        int sh = d & 1;
        ln2_kernel<<<NPOS / 8, 256>>>(e, w, ln1_g + d * C, ln1_b + d * C, sh ? 2 : 1, 1);
        gemm_mma<0,0,0,0,0,0><<<dim3(9, NPOS/128), 128>>>(
            w, wt + QO + (size_t)d*110592, qkv_b + d * 3 * C, qkv, e, 3 * C, C, 0);
        attn2_kernel<<<dim3(B * NW, HEADS), 256, ATTN_SMEM>>>(bias + (size_t)d * 98304, sh);
        // proj with fused un-window + residual add into e (staged PERM)
        gemm_mma<0,1,0,0,1,0><<<dim3(3, NPOS/128), 128>>>(
            o, wt + PO + (size_t)d*36864, proj_b + d * C, e, e, C, C, sh);
        ln2_kernel<<<NPOS / 8, 256>>>(e, qkv, ln2_g + d * C, ln2_b + d * C, 0, 1);
        gemm_mma<1,0,1,0,0,0><<<dim3(12, NPOS/128), 128>>>(
            qkv, wt + F1O + (size_t)d*147456, fc1_b + d * 4 * C, h, e, 4 * C, C, 0);
        if (d < DEPTH - 1) {
            gemm_mma<0,1,0,0,0,0><<<dim3(3, NPOS/128), 128>>>(
                h, wt + F2O + (size_t)d*147456, fc2_b + d * C, e, w, C, 4 * C, 0);
        } else {
            gemm_mma<0,1,0,1,0,0><<<dim3(3, NPOS/128), 128>>>(
                h, wt + F2O + (size_t)d*147456, fc2_b + d * C, e, w, C, 4 * C, 0);
        }
    }

    // reconstruction with fused scatter (staged SCAT)
    gemm_mma<0,0,0,0,0,1><<<dim3(2, NPOS/128), 128>>>(w, wt + RO, recb, out, out, 128, C, 0);
}

// round 16
// speedup vs baseline: 1.2648x; 1.1668x over previous
#include <cuda_runtime.h>
#include <math.h>
#include <stdint.h>

typedef unsigned long long ull;

// ---------------- problem constants ----------------
#define B 2
#define C 192
#define HEADS 6
#define ZP 32
#define NPOS (B*ZP*ZP*ZP)          // 65536
#define NW 256
#define DEPTH 4
#define TBL 675

// weight scratch offsets (floats)
#define QO 0
#define PO 442368
#define F1O 589824
#define F2O 1179648
#define RO 1769472
#define PEO 1794048
#define WT_TOTAL 1818624

// ---------------- scratch ----------------
__device__ float g_e  [(size_t)NPOS * C];
__device__ float g_w  [(size_t)NPOS * C];
__device__ float g_qkv[(size_t)NPOS * 3 * C];
__device__ float g_o  [(size_t)NPOS * C];
__device__ float g_h  [(size_t)NPOS * 4 * C];
__device__ float g_wt [WT_TOTAL];
__device__ float g_bias[DEPTH * HEADS * 128 * 128];
__device__ float g_zeros[192];

// ---------------- helpers ----------------
__device__ __forceinline__ float gelu_f(float v){
    return 0.5f * v * (1.0f + erff(v * 0.70710678118654752f));
}
__device__ __forceinline__ void mma_tf32(float* d, const uint32_t* a, const uint32_t* b){
    asm volatile(
        "mma.sync.aligned.m16n8k8.row.col.f32.tf32.tf32.f32 "
        "{%0,%1,%2,%3}, {%4,%5,%6,%7}, {%8,%9}, {%0,%1,%2,%3};"
        : "+f"(d[0]), "+f"(d[1]), "+f"(d[2]), "+f"(d[3])
        : "r"(a[0]), "r"(a[1]), "r"(a[2]), "r"(a[3]), "r"(b[0]), "r"(b[1]));
}
__device__ __forceinline__ float tf32_rna(float x){
    uint32_t r; asm("cvt.rna.tf32.f32 %0, %1;" : "=r"(r) : "f"(x));
    return __uint_as_float(r);
}
__device__ __forceinline__ uint32_t smem_u32(const void* p){
    uint32_t a;
    asm("{ .reg .u64 t; cvta.to.shared.u64 t, %1; cvt.u32.u64 %0, t; }" : "=r"(a) : "l"(p));
    return a;
}
__device__ __forceinline__ void cp16(uint32_t d, const void* s){
    asm volatile("cp.async.cg.shared.global [%0], [%1], 16;" :: "r"(d), "l"(s));
}
__device__ __forceinline__ void cp_commit(){
    asm volatile("cp.async.commit_group;");
}
template<int Npend>
__device__ __forceinline__ void cp_wait(){
    asm volatile("cp.async.wait_group %0;" :: "n"(Npend) : "memory");
}

// ================= fused setup: weight transposes + rounding + bias table =================
__global__ void setup_kernel(const float* __restrict__ qkv_w, const float* __restrict__ proj_w,
                             const float* __restrict__ fc1_w, const float* __restrict__ fc2_w,
                             const float* __restrict__ rec_w, const float* __restrict__ pe_w,
                             const float* __restrict__ rpb)
{
    int idx = blockIdx.x * 256 + threadIdx.x;
    if (idx < 442368) {
        int d = idx / 110592, r = idx % 110592;
        int k = r / 576, n = r % 576;
        g_wt[QO + d * 110592 + n * 192 + k] = tf32_rna(qkv_w[idx]);
        return;
    }
    idx -= 442368;
    if (idx < 147456) {
        int d = idx / 36864, r = idx % 36864;
        int k = r / 192, n = r % 192;
        g_wt[PO + d * 36864 + n * 192 + k] = tf32_rna(proj_w[idx]);
        return;
    }
    idx -= 147456;
    if (idx < 589824) {
        int d = idx / 147456, r = idx % 147456;
        int k = r / 768, n = r % 768;
        g_wt[F1O + d * 147456 + n * 192 + k] = tf32_rna(fc1_w[idx]);
        return;
    }
    idx -= 589824;
    if (idx < 589824) {
        int d = idx / 147456, r = idx % 147456;
        int k = r / 192, n = r % 192;
        g_wt[F2O + d * 147456 + n * 768 + k] = tf32_rna(fc2_w[idx]);
        return;
    }
    idx -= 589824;
    if (idx < 24576) {
        int k = idx / 128, n = idx % 128;
        g_wt[RO + n * 192 + k] = tf32_rna(rec_w[idx]);
        return;
    }
    idx -= 24576;
    if (idx < 24576) {
        g_wt[PEO + idx] = tf32_rna(pe_w[idx]);
        return;
    }
    idx -= 24576;
    if (idx < DEPTH * HEADS * 16384) {
        int d = idx / 98304, r = idx % 98304;
        int h = r >> 14, n = (r >> 7) & 127, m = r & 127;
        int zn = n >> 6, hn = (n >> 3) & 7, wn = n & 7;
        int zm = m >> 6, hm = (m >> 3) & 7, wm = m & 7;
        int bi = (zn - zm + 1) * 225 + (hn - hm + 7) * 15 + (wn - wm + 7);
        g_bias[idx] = rpb[((size_t)d * TBL + bi) * HEADS + h];
    }
}
#define SETUP_TOTAL (442368 + 147456 + 589824 + 589824 + 24576 + 24576 + DEPTH*HEADS*16384)

// ================= tf32 mma.sync GEMM (R12 config) =================
#define ASZB (128 * 36 * 4)
#define BSZB (64 * 36 * 4)
template<int ACT, int BETA, int ROUT, int DUAL>
__global__ __launch_bounds__(128)
void gemm_mma(const float* __restrict__ A, const float* __restrict__ Bw,
              const float* __restrict__ bias, float* __restrict__ Cm,
              float* __restrict__ Cm2, int N, int K)
{
    __shared__ float As[2][128 * 36];
    __shared__ float Bs[2][64 * 36];
    const int t = threadIdx.x;
    const int lane = t & 31, wid = t >> 5;
    const int warpM = wid * 32;
    const int g = lane >> 2, tg = lane & 3;
    const int bm = blockIdx.y << 7;
    const int bn = blockIdx.x << 6;
    const int K4 = K >> 2;
    const int nk = K >> 5;

    const float4* A4 = (const float4*)A;
    const float4* B4 = (const float4*)Bw;
    const int lrow = t >> 3;
    const int lk4  = t & 7;
    int aBase[8], aOff[8];
#pragma unroll
    for (int i = 0; i < 8; i++) {
        int row = lrow + i * 16;
        aBase[i] = (bm + row) * K4 + lk4;
        aOff[i] = (row * 36 + lk4 * 4) * 4;
    }
    int bBase[4], bOff[4];
#pragma unroll
    for (int i = 0; i < 4; i++) {
        int row = lrow + i * 16;
        bBase[i] = (bn + row) * K4 + lk4;
        bOff[i] = (row * 36 + lk4 * 4) * 4;
    }
    const uint32_t uA = smem_u32(&As[0][0]);
    const uint32_t uB = smem_u32(&Bs[0][0]);

#pragma unroll
    for (int i = 0; i < 8; i++) cp16(uA + aOff[i], &A4[aBase[i]]);
#pragma unroll
    for (int i = 0; i < 4; i++) cp16(uB + bOff[i], &B4[bBase[i]]);
    cp_commit();

    float acc[2][8][4];
#pragma unroll
    for (int mi = 0; mi < 2; mi++)
#pragma unroll
        for (int ni = 0; ni < 8; ni++)
#pragma unroll
            for (int j = 0; j < 4; j++) acc[mi][ni][j] = 0.f;

    for (int kt = 0; kt < nk; kt++) {
        cp_wait<0>();
        __syncthreads();
        const int buf = kt & 1;
        if (kt + 1 < nk) {
            const int nb = buf ^ 1;
            const int ko = (kt + 1) * 8;
#pragma unroll
            for (int i = 0; i < 8; i++) cp16(uA + nb * ASZB + aOff[i], &A4[aBase[i] + ko]);
#pragma unroll
            for (int i = 0; i < 4; i++) cp16(uB + nb * BSZB + bOff[i], &B4[bBase[i] + ko]);
            cp_commit();
        }
        const uint32_t* Asu = (const uint32_t*)As[buf];
        const uint32_t* Bsu = (const uint32_t*)Bs[buf];
#pragma unroll
        for (int ks = 0; ks < 4; ks++) {
            const int k0 = ks * 8;
            uint32_t af[2][4];
#pragma unroll
            for (int mi = 0; mi < 2; mi++) {
                int r = (warpM + mi * 16 + g) * 36 + k0 + tg;
                af[mi][0] = Asu[r];
                af[mi][1] = Asu[r + 8 * 36];
                af[mi][2] = Asu[r + 4];
                af[mi][3] = Asu[r + 8 * 36 + 4];
            }
#pragma unroll
            for (int ni = 0; ni < 8; ni++) {
                uint32_t bf[2];
                int r = (ni * 8 + g) * 36 + k0 + tg;
                bf[0] = Bsu[r];
                bf[1] = Bsu[r + 4];
                mma_tf32(acc[0][ni], af[0], bf);
                mma_tf32(acc[1][ni], af[1], bf);
            }
        }
        __syncthreads();
    }

#pragma unroll
    for (int mi = 0; mi < 2; mi++) {
        int r0 = bm + warpM + mi * 16 + g;
#pragma unroll
        for (int ni = 0; ni < 8; ni++) {
            int cb = bn + ni * 8 + 2 * tg;
            float b0 = bias[cb], b1 = bias[cb + 1];
            float v0 = acc[mi][ni][0] + b0, v1 = acc[mi][ni][1] + b1;
            float v2 = acc[mi][ni][2] + b0, v3 = acc[mi][ni][3] + b1;
            if (ACT) { v0 = gelu_f(v0); v1 = gelu_f(v1); v2 = gelu_f(v2); v3 = gelu_f(v3); }
            if (ROUT) { v0 = tf32_rna(v0); v1 = tf32_rna(v1); v2 = tf32_rna(v2); v3 = tf32_rna(v3); }
            size_t o0 = (size_t)r0 * N + cb;
            size_t o1 = (size_t)(r0 + 8) * N + cb;
            if (BETA) {
                float2 x0 = *(const float2*)&Cm[o0];
                float2 x1 = *(const float2*)&Cm[o1];
                v0 += x0.x; v1 += x0.y; v2 += x1.x; v3 += x1.y;
            }
            *(float2*)&Cm[o0] = make_float2(v0, v1);
            *(float2*)&Cm[o1] = make_float2(v2, v3);
            if (DUAL) {
                *(float2*)&Cm2[o0] = make_float2(tf32_rna(v0), tf32_rna(v1));
                *(float2*)&Cm2[o1] = make_float2(tf32_rna(v2), tf32_rna(v3));
            }
        }
    }
}

// ---------------- warp-per-token LayerNorm ----------------
__global__ __launch_bounds__(256)
void ln2_kernel(const float* __restrict__ src, float* __restrict__ dst,
                const float* __restrict__ g, const float* __restrict__ b, int mode, int rnd)
{
    const int lane = threadIdx.x & 31;
    const int tok = blockIdx.x * 8 + (threadIdx.x >> 5);
    int spos;
    if (mode == 0) {
        spos = tok;
    } else {
        int n = tok & 127, wi = (tok >> 7) & 255, bb = tok >> 15;
        int zw = wi >> 4, hw = (wi >> 2) & 3, ww = wi & 3;
        int z = zw * 2 + (n >> 6), h = hw * 8 + ((n >> 3) & 7), w = ww * 8 + (n & 7);
        if (mode == 2) { z = (z + 1) & 31; h = (h + 4) & 31; w = (w + 4) & 31; }
        spos = ((bb * 32 + z) * 32 + h) * 32 + w;
    }
    const float* sp = src + (size_t)spos * C;
    float v[6]; float s = 0.f, s2 = 0.f;
#pragma unroll
    for (int j = 0; j < 6; j++) { v[j] = sp[lane + 32*j]; s += v[j]; s2 += v[j]*v[j]; }
#pragma unroll
    for (int o = 16; o > 0; o >>= 1) {
        s  += __shfl_xor_sync(0xffffffffu, s,  o);
        s2 += __shfl_xor_sync(0xffffffffu, s2, o);
    }
    float m = s * (1.0f/192.0f);
    float rstd = rsqrtf(s2 * (1.0f/192.0f) - m*m + 1e-5f);
    float* dp = dst + (size_t)tok * C;
#pragma unroll
    for (int j = 0; j < 6; j++) {
        int c = lane + 32*j;
        float o2 = (v[j] - m) * rstd * g[c] + b[c];
        dp[c] = rnd ? tf32_rna(o2) : o2;
    }
}

// ---------------- fused window-merge + residual add + LayerNorm (dst rounded) ----------------
__global__ __launch_bounds__(256)
void lnfuse_kernel(float* __restrict__ e, const float* __restrict__ wwin,
                   float* __restrict__ dst,
                   const float* __restrict__ g, const float* __restrict__ b, int shifted)
{
    const int lane = threadIdx.x & 31;
    const int pos = blockIdx.x * 8 + (threadIdx.x >> 5);
    int ww2 = pos & 31, hh = (pos >> 5) & 31, z = (pos >> 10) & 31, bb = pos >> 15;
    int sz = shifted ? 1 : 0, s4 = shifted ? 4 : 0;
    int z2 = (z - sz) & 31, h2 = (hh - s4) & 31, w2 = (ww2 - s4) & 31;
    int wi = ((z2 >> 1) << 4) | ((h2 >> 3) << 2) | (w2 >> 3);
    int n  = ((z2 & 1) << 6) | ((h2 & 7) << 3) | (w2 & 7);
    int tok = (bb * 256 + wi) * 128 + n;

    float* ep = e + (size_t)pos * C;
    const float* wp = wwin + (size_t)tok * C;
    float v[6]; float s = 0.f, s2 = 0.f;
#pragma unroll
    for (int j = 0; j < 6; j++) {
        int c = lane + 32*j;
        float a = ep[c] + wp[c];
        ep[c] = a;
        v[j] = a; s += a; s2 += a*a;
    }
#pragma unroll
    for (int o = 16; o > 0; o >>= 1) {
        s  += __shfl_xor_sync(0xffffffffu, s,  o);
        s2 += __shfl_xor_sync(0xffffffffu, s2, o);
    }
    float m = s * (1.0f/192.0f);
    float rstd = rsqrtf(s2 * (1.0f/192.0f) - m*m + 1e-5f);
    float* dp = dst + (size_t)pos * C;
#pragma unroll
    for (int j = 0; j < 6; j++) {
        int c = lane + 32*j;
        dp[c] = tf32_rna((v[j] - m) * rstd * g[c] + b[c]);
    }
}

// ---------------- window attention: full tf32 MMA, Ss aliases Qn/Kn (85KB smem) ----------------
// layout (floats): Ss [128][132] at 0 (16896); Qn [128][36] at 0; Kn at 4608;
//                  Vt [32][132] at 16896; rid at 21120
#define OS 0
#define OQ 0
#define OK_ 4608
#define OV 16896
#define ORID 21120
#define ATTN_SMEM_F 21256

__global__ __launch_bounds__(256)
void attn2_kernel(const float* __restrict__ biasT, int shifted)
{
    extern __shared__ float sm[];
    float* Qn = sm + OQ;
    float* Kn = sm + OK_;
    float* Vt = sm + OV;
    float* Ss = sm + OS;
    int* rid_s = (int*)(sm + ORID);

    const int win = blockIdx.x;
    const int hh  = blockIdx.y;
    const int t = threadIdx.x;
    const int lane = t & 31, wid = t >> 5;
    const int g = lane >> 2, tg = lane & 3;
    const float scale = 0.1767766952966369f;
    const float* bl = biasT + (size_t)hh * 16384;

    for (int e = t; e < 4096; e += 256) {
        int n = e >> 5, d = e & 31;
        size_t base = ((size_t)(win * 128 + n)) * (3 * C) + hh * 32 + d;
        Qn[n * 36 + d] = tf32_rna(g_qkv[base] * scale);
        Kn[n * 36 + d] = tf32_rna(g_qkv[base + C]);
        Vt[d * 132 + n] = tf32_rna(g_qkv[base + 2 * C]);
    }
    int wloc = win & 255;
    int zw = wloc >> 4, hw = (wloc >> 2) & 3, ww = wloc & 3;
    if (shifted && t < 128) {
        int z = zw * 2 + (t >> 6), h = hw * 8 + ((t >> 3) & 7), w = ww * 8 + (t & 7);
        rid_s[t] = (z < 30 ? 0 : (z < 31 ? 1 : 2)) * 9
                 + (h < 24 ? 0 : (h < 28 ? 1 : 2)) * 3
                 + (w < 24 ? 0 : (w < 28 ? 1 : 2));
    }
    __syncthreads();

    // ---- S = QK^T via tf32 mma ----
    {
        float sacc[16][4];
#pragma unroll
        for (int mi = 0; mi < 16; mi++)
#pragma unroll
            for (int j = 0; j < 4; j++) sacc[mi][j] = 0.f;
        const uint32_t* Qu = (const uint32_t*)Qn;
        const uint32_t* Ku = (const uint32_t*)Kn;
#pragma unroll
        for (int ks = 0; ks < 4; ks++) {
            const int k0 = ks * 8;
            uint32_t af[4];
            int ra = (wid * 16 + g) * 36 + k0 + tg;
            af[0] = Qu[ra];
            af[1] = Qu[ra + 8 * 36];
            af[2] = Qu[ra + 4];
            af[3] = Qu[ra + 8 * 36 + 4];
#pragma unroll
            for (int mi = 0; mi < 16; mi++) {
                uint32_t bf[2];
                int rb = (mi * 8 + g) * 36 + k0 + tg;
                bf[0] = Ku[rb];
                bf[1] = Ku[rb + 4];
                mma_tf32(sacc[mi], af, bf);
            }
        }
        __syncthreads();   // all warps done reading Qn/Kn before Ss overwrites them
        int n0 = wid * 16 + g;
        int ridn0 = shifted ? rid_s[n0] : 0;
        int ridn1 = shifted ? rid_s[n0 + 8] : 0;
#pragma unroll
        for (int mi = 0; mi < 16; mi++) {
            int mb = mi * 8 + 2 * tg;
            float2 b0 = *(const float2*)&bl[n0 * 128 + mb];
            float2 b1 = *(const float2*)&bl[(n0 + 8) * 128 + mb];
            float v0 = sacc[mi][0] + b0.x, v1 = sacc[mi][1] + b0.y;
            float v2 = sacc[mi][2] + b1.x, v3 = sacc[mi][3] + b1.y;
            if (shifted) {
                int rm0 = rid_s[mb], rm1 = rid_s[mb + 1];
                if (rm0 != ridn0) v0 -= 100.0f;
                if (rm1 != ridn0) v1 -= 100.0f;
                if (rm0 != ridn1) v2 -= 100.0f;
                if (rm1 != ridn1) v3 -= 100.0f;
            }
            *(float2*)&Ss[n0 * 132 + mb] = make_float2(v0, v1);
            *(float2*)&Ss[(n0 + 8) * 132 + mb] = make_float2(v2, v3);
        }
    }
    __syncthreads();

    // ---- softmax (rounds P to tf32) ----
    {
        int n = t >> 1, half = t & 1;
        float* row = &Ss[n * 132 + half * 64];
        float mx = -1e30f;
#pragma unroll
        for (int j = 0; j < 16; j++) {
            float4 v = *(const float4*)&row[j * 4];
            mx = fmaxf(mx, fmaxf(fmaxf(v.x, v.y), fmaxf(v.z, v.w)));
        }
        mx = fmaxf(mx, __shfl_xor_sync(0xffffffffu, mx, 1));
        float sum = 0.f;
#pragma unroll
        for (int j = 0; j < 16; j++) {
            float4 v = *(float4*)&row[j * 4];
            v.x = __expf(v.x - mx); v.y = __expf(v.y - mx);
            v.z = __expf(v.z - mx); v.w = __expf(v.w - mx);
            sum += v.x + v.y + v.z + v.w;
            *(float4*)&row[j * 4] = v;
        }
        sum += __shfl_xor_sync(0xffffffffu, sum, 1);
        float inv = 1.0f / sum;
#pragma unroll
        for (int j = 0; j < 16; j++) {
            float4 v = *(float4*)&row[j * 4];
            v.x = tf32_rna(v.x * inv); v.y = tf32_rna(v.y * inv);
            v.z = tf32_rna(v.z * inv); v.w = tf32_rna(v.w * inv);
            *(float4*)&row[j * 4] = v;
        }
    }
    __syncthreads();

    // ---- O = P @ V via tf32 mma ----
    {
        float av[4][4];
#pragma unroll
        for (int ni = 0; ni < 4; ni++)
#pragma unroll
            for (int j = 0; j < 4; j++) av[ni][j] = 0.f;
        const uint32_t* Ps = (const uint32_t*)Ss;
        const uint32_t* Vu = (const uint32_t*)Vt;
#pragma unroll
        for (int ks = 0; ks < 16; ks++) {
            const int k0 = ks * 8;
            uint32_t af[4];
            int ra = (wid * 16 + g) * 132 + k0 + tg;
            af[0] = Ps[ra];
            af[1] = Ps[ra + 8 * 132];
            af[2] = Ps[ra + 4];
            af[3] = Ps[ra + 8 * 132 + 4];
#pragma unroll
            for (int ni = 0; ni < 4; ni++) {
                uint32_t bf[2];
                int rb = (ni * 8 + g) * 132 + k0 + tg;
                bf[0] = Vu[rb];
                bf[1] = Vu[rb + 4];
                mma_tf32(av[ni], af, bf);
            }
        }
#pragma unroll
        for (int ni = 0; ni < 4; ni++) {
            int n0 = wid * 16 + g;
            int d = ni * 8 + 2 * tg;
            size_t o0 = ((size_t)(win * 128 + n0)) * C + hh * 32 + d;
            size_t o1 = ((size_t)(win * 128 + n0 + 8)) * C + hh * 32 + d;
            *(float2*)&g_o[o0] = make_float2(tf32_rna(av[ni][0]), tf32_rna(av[ni][1]));
            *(float2*)&g_o[o1] = make_float2(tf32_rna(av[ni][2]), tf32_rna(av[ni][3]));
        }
    }
}

// ---------------- patch-embed gather (rounded) / recon scatter ----------------
__global__ void gather_kernel(const float* __restrict__ x, float* __restrict__ xg)
{
    int idx = blockIdx.x * blockDim.x + threadIdx.x;
    if (idx >= NPOS * 128) return;
    int t = idx & 127, pos = idx >> 7;
    int w = pos & 31, h = (pos >> 5) & 31, z = (pos >> 10) & 31, b = pos >> 15;
    int c4 = t >> 5, i = (t >> 4) & 1, j = (t >> 2) & 3, k = t & 3;
    xg[idx] = tf32_rna(x[((((size_t)b * 4 + c4) * 64 + 2 * z + i) * 128 + 4 * h + j) * 128 + 4 * w + k]);
}

__global__ void scatter_kernel(const float* __restrict__ rec, const float* __restrict__ rec_b,
                               float* __restrict__ out)
{
    int idx = blockIdx.x * blockDim.x + threadIdx.x;
    if (idx >= NPOS * 128) return;
    int t = idx & 127, pos = idx >> 7;
    int w = pos & 31, h = (pos >> 5) & 31, z = (pos >> 10) & 31, b = pos >> 15;
    int o = t >> 5, i = (t >> 4) & 1, j = (t >> 2) & 3, k = t & 3;
    out[((((size_t)b * 4 + o) * 64 + 2 * z + i) * 128 + 4 * h + j) * 128 + 4 * w + k]
        = rec[idx] + rec_b[o];
}

// ---------------- host launcher ----------------
extern "C" void kernel_launch(void* const* d_in, const int* in_sizes, int n_in,
                              void* d_out, int out_size)
{
    const float* x       = (const float*)d_in[0];
    const float* pe_w    = (const float*)d_in[1];
    const float* pe_b    = (const float*)d_in[2];
    const float* pe_ln_g = (const float*)d_in[3];
    const float* pe_ln_b = (const float*)d_in[4];
    const float* ln1_g   = (const float*)d_in[5];
    const float* ln1_b   = (const float*)d_in[6];
    const float* qkv_w   = (const float*)d_in[7];
    const float* qkv_b   = (const float*)d_in[8];
    const float* proj_w  = (const float*)d_in[9];
    const float* proj_b  = (const float*)d_in[10];
    const float* rpb     = (const float*)d_in[11];
    const float* ln2_g   = (const float*)d_in[12];
    const float* ln2_b   = (const float*)d_in[13];
    const float* fc1_w   = (const float*)d_in[14];
    const float* fc1_b   = (const float*)d_in[15];
    const float* fc2_w   = (const float*)d_in[16];
    const float* fc2_b   = (const float*)d_in[17];
    const float* rec_w   = (const float*)d_in[18];
    const float* rec_b   = (const float*)d_in[19];
    float* out = (float*)d_out;

    float *e, *w, *qkv, *h, *o, *wt, *bias, *zeros;
    cudaGetSymbolAddress((void**)&e,     g_e);
    cudaGetSymbolAddress((void**)&w,     g_w);
    cudaGetSymbolAddress((void**)&qkv,   g_qkv);
    cudaGetSymbolAddress((void**)&h,     g_h);
    cudaGetSymbolAddress((void**)&o,     g_o);
    cudaGetSymbolAddress((void**)&wt,    g_wt);
    cudaGetSymbolAddress((void**)&bias,  g_bias);
    cudaGetSymbolAddress((void**)&zeros, g_zeros);

    const int ATTN_SMEM = ATTN_SMEM_F * (int)sizeof(float);
    cudaFuncSetAttribute(attn2_kernel, cudaFuncAttributeMaxDynamicSharedMemorySize, ATTN_SMEM);

    setup_kernel<<<(SETUP_TOTAL + 255) / 256, 256>>>(qkv_w, proj_w, fc1_w, fc2_w, rec_w, pe_w, rpb);

    gather_kernel<<<(NPOS * 128) / 256, 256>>>(x, h);
    gemm_mma<0,0,0,0><<<dim3(3, NPOS/128), 128>>>(h, wt + PEO, pe_b, w, e, 192, 128);
    ln2_kernel<<<NPOS / 8, 256>>>(w, e, pe_ln_g, pe_ln_b, 0, 0);

    for (int d = 0; d < DEPTH; d++) {
        int sh = d & 1;
        ln2_kernel<<<NPOS / 8, 256>>>(e, w, ln1_g + d * C, ln1_b + d * C, sh ? 2 : 1, 1);
        gemm_mma<0,0,0,0><<<dim3(9, NPOS/128), 128>>>(
            w, wt + QO + (size_t)d*110592, qkv_b + d * 3 * C, qkv, e, 3 * C, C);
        attn2_kernel<<<dim3(B * NW, HEADS), 256, ATTN_SMEM>>>(bias + (size_t)d * 98304, sh);
        gemm_mma<0,0,0,0><<<dim3(3, NPOS/128), 128>>>(
            o, wt + PO + (size_t)d*36864, proj_b + d * C, w, e, C, C);
        lnfuse_kernel<<<NPOS / 8, 256>>>(e, w, qkv, ln2_g + d * C, ln2_b + d * C, sh);
        gemm_mma<1,0,1,0><<<dim3(12, NPOS/128), 128>>>(
            qkv, wt + F1O + (size_t)d*147456, fc1_b + d * 4 * C, h, e, 4 * C, C);
        if (d < DEPTH - 1) {
            gemm_mma<0,1,0,0><<<dim3(3, NPOS/128), 128>>>(
                h, wt + F2O + (size_t)d*147456, fc2_b + d * C, e, w, C, 4 * C);
        } else {
            gemm_mma<0,1,0,1><<<dim3(3, NPOS/128), 128>>>(
                h, wt + F2O + (size_t)d*147456, fc2_b + d * C, e, w, C, 4 * C);
        }
    }

    gemm_mma<0,0,0,0><<<dim3(2, NPOS/128), 128>>>(w, wt + RO, zeros, qkv, e, 128, C);
    scatter_kernel<<<(NPOS * 128) / 256, 256>>>(qkv, rec_b, out);
}